// round 4
// baseline (speedup 1.0000x reference)
#include <cuda_runtime.h>
#include <math.h>

#define NL 6
#define NH 16
#define DM 768
#define DFF 3072
#define NB 4
#define NTOKS 1023
#define SEQ 1024
#define HDIM 48
#define MTOK (NB * SEQ)      // 4096 tokens
#define LN_EPS 1e-5f

// ---------------- scratch (device globals; no allocation APIs) ----------------
__device__ float g_x[MTOK * DM];          // residual stream
__device__ float g_h[MTOK * DM];          // LN output
__device__ float g_qkv[MTOK * 3 * DM];    // qkv projections
__device__ float g_o[MTOK * DM];          // attention output
__device__ float g_act[MTOK * DFF];       // silu(gate)*up

// ---------------- embed: x = concat(cls_token, cls_tokens) ----------------
__global__ void embed_kernel(const float* __restrict__ cls_tokens,
                             const float* __restrict__ cls_token) {
    int idx = blockIdx.x * blockDim.x + threadIdx.x;
    if (idx >= MTOK * DM) return;
    int d = idx % DM;
    int tok = idx / DM;
    int b = tok / SEQ, s = tok % SEQ;
    g_x[idx] = (s == 0) ? cls_token[d]
                        : cls_tokens[(b * NTOKS + (s - 1)) * DM + d];
}

// ---------------- layernorm: one block per row, 256 threads ----------------
__global__ void ln_kernel(const float* __restrict__ src, int src_row_stride,
                          float* __restrict__ dst,
                          const float* __restrict__ w,
                          const float* __restrict__ bias) {
    int row = blockIdx.x;
    const float* xp = src + (long)row * src_row_stride;
    float* yp = dst + (long)row * DM;
    int tid = threadIdx.x;  // 256
    float v0 = xp[tid], v1 = xp[tid + 256], v2 = xp[tid + 512];
    float s1 = v0 + v1 + v2;
    float s2 = v0 * v0 + v1 * v1 + v2 * v2;
#pragma unroll
    for (int off = 16; off > 0; off >>= 1) {
        s1 += __shfl_xor_sync(0xffffffff, s1, off);
        s2 += __shfl_xor_sync(0xffffffff, s2, off);
    }
    __shared__ float sm1[8], sm2[8];
    int wid = tid >> 5, lid = tid & 31;
    if (lid == 0) { sm1[wid] = s1; sm2[wid] = s2; }
    __syncthreads();
    if (wid == 0) {
        float t1 = (lid < 8) ? sm1[lid] : 0.f;
        float t2 = (lid < 8) ? sm2[lid] : 0.f;
#pragma unroll
        for (int off = 4; off > 0; off >>= 1) {
            t1 += __shfl_xor_sync(0xffffffff, t1, off);
            t2 += __shfl_xor_sync(0xffffffff, t2, off);
        }
        if (lid == 0) { sm1[0] = t1; sm2[0] = t2; }
    }
    __syncthreads();
    float mean = sm1[0] * (1.f / DM);
    float var = sm2[0] * (1.f / DM) - mean * mean;
    float rstd = rsqrtf(var + LN_EPS);
    yp[tid]       = (v0 - mean) * rstd * w[tid]       + bias[tid];
    yp[tid + 256] = (v1 - mean) * rstd * w[tid + 256] + bias[tid + 256];
    yp[tid + 512] = (v2 - mean) * rstd * w[tid + 512] + bias[tid + 512];
}

// ---------------- GEMM (NT): C[m,n] = sum_k A[m,k]*B[n,k] (+ residual) -------
// 64x64x16 tile, 128 threads, per-thread 4x8 micro-tile.
// smem tiles stored K-major: As[k][m] so mainloop reads are LDS.128 conflict-free.
template <bool RESID>
__global__ void __launch_bounds__(128)
gemm_nt(const float* __restrict__ A, const float* __restrict__ Bm,
        const float* __restrict__ Rin, float* __restrict__ Cm,
        int Ndim, int Kdim) {
    __shared__ float As[16][64];
    __shared__ float Bs[16][64];
    int tid = threadIdx.x;
    int m0 = blockIdx.y * 64, n0 = blockIdx.x * 64;
    int a = tid >> 3;   // 0..15 : row group
    int b8 = tid & 7;   // 0..7  : col group
    float acc[4][8];
#pragma unroll
    for (int r = 0; r < 4; r++)
#pragma unroll
        for (int c = 0; c < 8; c++) acc[r][c] = 0.f;

    const float* Ab = A + (long)m0 * Kdim;
    const float* Bb = Bm + (long)n0 * Kdim;

    for (int k0 = 0; k0 < Kdim; k0 += 16) {
#pragma unroll
        for (int i = 0; i < 2; i++) {
            int idx = tid * 2 + i;        // 0..255
            int row = idx >> 2;           // 0..63
            int kk = (idx & 3) * 4;       // 0,4,8,12
            float4 va = *(const float4*)(Ab + (long)row * Kdim + k0 + kk);
            As[kk + 0][row] = va.x; As[kk + 1][row] = va.y;
            As[kk + 2][row] = va.z; As[kk + 3][row] = va.w;
            float4 vb = *(const float4*)(Bb + (long)row * Kdim + k0 + kk);
            Bs[kk + 0][row] = vb.x; Bs[kk + 1][row] = vb.y;
            Bs[kk + 2][row] = vb.z; Bs[kk + 3][row] = vb.w;
        }
        __syncthreads();
#pragma unroll
        for (int k = 0; k < 16; k++) {
            float4 av = *(const float4*)&As[k][a * 4];
            float4 bv0 = *(const float4*)&Bs[k][b8 * 4];
            float4 bv1 = *(const float4*)&Bs[k][32 + b8 * 4];
            float ar[4] = {av.x, av.y, av.z, av.w};
            float br[8] = {bv0.x, bv0.y, bv0.z, bv0.w,
                           bv1.x, bv1.y, bv1.z, bv1.w};
#pragma unroll
            for (int r = 0; r < 4; r++)
#pragma unroll
                for (int c = 0; c < 8; c++) acc[r][c] += ar[r] * br[c];
        }
        __syncthreads();
    }
#pragma unroll
    for (int r = 0; r < 4; r++) {
        int m = m0 + a * 4 + r;
        float* crow = Cm + (long)m * Ndim + n0;
#pragma unroll
        for (int half = 0; half < 2; half++) {
            int coff = half * 32 + b8 * 4;
            float4 o;
            o.x = acc[r][half * 4 + 0]; o.y = acc[r][half * 4 + 1];
            o.z = acc[r][half * 4 + 2]; o.w = acc[r][half * 4 + 3];
            if (RESID) {
                float4 rv = *(const float4*)(Rin + (long)m * Ndim + n0 + coff);
                o.x += rv.x; o.y += rv.y; o.z += rv.z; o.w += rv.w;
            }
            *(float4*)(crow + coff) = o;
        }
    }
}

// ---------------- fused gate/up GEMM + SiLU ----------------
__global__ void __launch_bounds__(128)
gemm_gateup(const float* __restrict__ Hm, const float* __restrict__ Wg,
            const float* __restrict__ Wu, float* __restrict__ Act) {
    __shared__ float As[16][64];
    __shared__ float Gs[16][64];
    __shared__ float Us[16][64];
    int tid = threadIdx.x;
    int m0 = blockIdx.y * 64, n0 = blockIdx.x * 64;
    int a = tid >> 3, b8 = tid & 7;
    float ag[4][8], au[4][8];
#pragma unroll
    for (int r = 0; r < 4; r++)
#pragma unroll
        for (int c = 0; c < 8; c++) { ag[r][c] = 0.f; au[r][c] = 0.f; }

    const float* Ab = Hm + (long)m0 * DM;
    const float* Gb = Wg + (long)n0 * DM;
    const float* Ub = Wu + (long)n0 * DM;

    for (int k0 = 0; k0 < DM; k0 += 16) {
#pragma unroll
        for (int i = 0; i < 2; i++) {
            int idx = tid * 2 + i;
            int row = idx >> 2;
            int kk = (idx & 3) * 4;
            float4 va = *(const float4*)(Ab + (long)row * DM + k0 + kk);
            As[kk + 0][row] = va.x; As[kk + 1][row] = va.y;
            As[kk + 2][row] = va.z; As[kk + 3][row] = va.w;
            float4 vg = *(const float4*)(Gb + (long)row * DM + k0 + kk);
            Gs[kk + 0][row] = vg.x; Gs[kk + 1][row] = vg.y;
            Gs[kk + 2][row] = vg.z; Gs[kk + 3][row] = vg.w;
            float4 vu = *(const float4*)(Ub + (long)row * DM + k0 + kk);
            Us[kk + 0][row] = vu.x; Us[kk + 1][row] = vu.y;
            Us[kk + 2][row] = vu.z; Us[kk + 3][row] = vu.w;
        }
        __syncthreads();
#pragma unroll
        for (int k = 0; k < 16; k++) {
            float4 av = *(const float4*)&As[k][a * 4];
            float4 g0 = *(const float4*)&Gs[k][b8 * 4];
            float4 g1 = *(const float4*)&Gs[k][32 + b8 * 4];
            float4 u0 = *(const float4*)&Us[k][b8 * 4];
            float4 u1 = *(const float4*)&Us[k][32 + b8 * 4];
            float ar[4] = {av.x, av.y, av.z, av.w};
            float gr[8] = {g0.x, g0.y, g0.z, g0.w, g1.x, g1.y, g1.z, g1.w};
            float ur[8] = {u0.x, u0.y, u0.z, u0.w, u1.x, u1.y, u1.z, u1.w};
#pragma unroll
            for (int r = 0; r < 4; r++)
#pragma unroll
                for (int c = 0; c < 8; c++) {
                    ag[r][c] += ar[r] * gr[c];
                    au[r][c] += ar[r] * ur[c];
                }
        }
        __syncthreads();
    }
#pragma unroll
    for (int r = 0; r < 4; r++) {
        int m = m0 + a * 4 + r;
        float* crow = Act + (long)m * DFF + n0;
#pragma unroll
        for (int half = 0; half < 2; half++) {
            int coff = half * 32 + b8 * 4;
            float4 o;
#pragma unroll
            for (int c = 0; c < 4; c++) {
                float g = ag[r][half * 4 + c];
                float u = au[r][half * 4 + c];
                float s = g / (1.f + __expf(-g));  // silu
                ((float*)&o)[c] = s * u;
            }
            *(float4*)(crow + coff) = o;
        }
    }
}

// ---------------- flash attention (fp32, online softmax, ALiBi) ----------------
// grid: (SEQ/64 q-tiles, B*H). 128 threads. 64x64 score tile, HD=48.
#define ATTN_SMEM_FLOATS 13760
#define ATTN_SMEM_BYTES (ATTN_SMEM_FLOATS * 4)

__global__ void __launch_bounds__(128)
attn_kernel(const float* __restrict__ log_slopes) {
    extern __shared__ float sm[];
    float (*Qs)[49] = (float(*)[49])sm;             // 64x49
    float (*Ks)[49] = (float(*)[49])(sm + 3136);    // 64x49
    float (*Vs)[49] = (float(*)[49])(sm + 6272);    // 64x49
    float (*Ps)[65] = (float(*)[65])(sm + 9408);    // 64x65
    float* mrow = sm + 13568;
    float* lrow = sm + 13632;
    float* crow = sm + 13696;

    int qt = blockIdx.x;
    int bh = blockIdx.y;
    int b = bh >> 4, h = bh & 15;
    int tid = threadIdx.x;
    int a = tid >> 3;   // 0..15
    int b8 = tid & 7;   // 0..7
    float slope = expf(log_slopes[h]);
    const float scale = 0.14433756729740643f;  // 1/sqrt(48)
    int q0 = qt * 64;
    const float* qkvb = g_qkv + (long)b * SEQ * (3 * DM);

    // load Q tile
    for (int i = tid; i < 64 * 12; i += 128) {
        int r = i / 12, c4 = (i % 12) * 4;
        float4 v = *(const float4*)(qkvb + (long)(q0 + r) * (3 * DM) + h * HDIM + c4);
        Qs[r][c4 + 0] = v.x; Qs[r][c4 + 1] = v.y;
        Qs[r][c4 + 2] = v.z; Qs[r][c4 + 3] = v.w;
    }
    if (tid < 64) { mrow[tid] = -1e30f; lrow[tid] = 0.f; }
    float oacc[4][6];
#pragma unroll
    for (int r = 0; r < 4; r++)
#pragma unroll
        for (int c = 0; c < 6; c++) oacc[r][c] = 0.f;
    __syncthreads();

    for (int kt = 0; kt < SEQ; kt += 64) {
        // load K, V tiles
        for (int i = tid; i < 64 * 12; i += 128) {
            int r = i / 12, c4 = (i % 12) * 4;
            const float* kp = qkvb + (long)(kt + r) * (3 * DM) + DM + h * HDIM + c4;
            float4 kv = *(const float4*)kp;
            Ks[r][c4 + 0] = kv.x; Ks[r][c4 + 1] = kv.y;
            Ks[r][c4 + 2] = kv.z; Ks[r][c4 + 3] = kv.w;
            float4 vv = *(const float4*)(kp + DM);
            Vs[r][c4 + 0] = vv.x; Vs[r][c4 + 1] = vv.y;
            Vs[r][c4 + 2] = vv.z; Vs[r][c4 + 3] = vv.w;
        }
        __syncthreads();

        // scores: 64x64 = (16x8 threads) x (4x8 micro-tile)
        float sacc[4][8];
#pragma unroll
        for (int r = 0; r < 4; r++)
#pragma unroll
            for (int c = 0; c < 8; c++) sacc[r][c] = 0.f;
#pragma unroll 8
        for (int k = 0; k < HDIM; k++) {
            float ar[4], br[8];
#pragma unroll
            for (int r = 0; r < 4; r++) ar[r] = Qs[a * 4 + r][k];
#pragma unroll
            for (int c = 0; c < 8; c++) br[c] = Ks[b8 * 8 + c][k];
#pragma unroll
            for (int r = 0; r < 4; r++)
#pragma unroll
                for (int c = 0; c < 8; c++) sacc[r][c] += ar[r] * br[c];
        }
#pragma unroll
        for (int r = 0; r < 4; r++)
#pragma unroll
            for (int c = 0; c < 8; c++) {
                int qi = q0 + a * 4 + r;
                int kj = kt + b8 * 8 + c;
                Ps[a * 4 + r][b8 * 8 + c] =
                    sacc[r][c] * scale - slope * fabsf((float)(qi - kj));
            }
        __syncthreads();

        // online softmax, one thread per row
        if (tid < 64) {
            int row = tid;
            float mold = mrow[row];
            float mx = mold;
#pragma unroll 8
            for (int j = 0; j < 64; j++) mx = fmaxf(mx, Ps[row][j]);
            float corr = __expf(mold - mx);
            float sum = 0.f;
#pragma unroll 8
            for (int j = 0; j < 64; j++) {
                float p = __expf(Ps[row][j] - mx);
                Ps[row][j] = p;
                sum += p;
            }
            lrow[row] = lrow[row] * corr + sum;
            mrow[row] = mx;
            crow[row] = corr;
        }
        __syncthreads();

        // o = o*corr + P @ V : per-thread 4 rows x 6 cols
        float cr[4];
#pragma unroll
        for (int r = 0; r < 4; r++) cr[r] = crow[a * 4 + r];
#pragma unroll
        for (int r = 0; r < 4; r++)
#pragma unroll
            for (int c = 0; c < 6; c++) oacc[r][c] *= cr[r];
#pragma unroll 8
        for (int j = 0; j < 64; j++) {
            float pv[4], vv[6];
#pragma unroll
            for (int r = 0; r < 4; r++) pv[r] = Ps[a * 4 + r][j];
#pragma unroll
            for (int c = 0; c < 6; c++) vv[c] = Vs[j][b8 * 6 + c];
#pragma unroll
            for (int r = 0; r < 4; r++)
#pragma unroll
                for (int c = 0; c < 6; c++) oacc[r][c] += pv[r] * vv[c];
        }
        __syncthreads();
    }

    // normalize + write: o[row][col] layout (b, s, h*HD + col)
#pragma unroll
    for (int r = 0; r < 4; r++) {
        int row = a * 4 + r;
        float inv = 1.f / lrow[row];
#pragma unroll
        for (int c = 0; c < 6; c++) {
            g_o[(long)(b * SEQ + q0 + row) * DM + h * HDIM + b8 * 6 + c] =
                oacc[r][c] * inv;
        }
    }
}

// ---------------- launch ----------------
extern "C" void kernel_launch(void* const* d_in, const int* in_sizes, int n_in,
                              void* d_out, int out_size) {
    (void)in_sizes; (void)n_in; (void)out_size;
    const float* cls_tokens = (const float*)d_in[0];
    const float* cls_token  = (const float*)d_in[1];
    const float* log_slopes = (const float*)d_in[2];
    const float* Wqkv = (const float*)d_in[3];
    const float* Wo   = (const float*)d_in[4];
    const float* Wg   = (const float*)d_in[5];
    const float* Wu   = (const float*)d_in[6];
    const float* Wd   = (const float*)d_in[7];
    const float* ln1w = (const float*)d_in[8];
    const float* ln1b = (const float*)d_in[9];
    const float* ln2w = (const float*)d_in[10];
    const float* ln2b = (const float*)d_in[11];
    const float* finw = (const float*)d_in[12];
    const float* finb = (const float*)d_in[13];
    float* out = (float*)d_out;

    float *px, *ph, *pqkv, *po, *pact;
    cudaGetSymbolAddress((void**)&px, g_x);
    cudaGetSymbolAddress((void**)&ph, g_h);
    cudaGetSymbolAddress((void**)&pqkv, g_qkv);
    cudaGetSymbolAddress((void**)&po, g_o);
    cudaGetSymbolAddress((void**)&pact, g_act);

    cudaFuncSetAttribute(attn_kernel,
                         cudaFuncAttributeMaxDynamicSharedMemorySize,
                         ATTN_SMEM_BYTES);

    embed_kernel<<<(MTOK * DM + 255) / 256, 256>>>(cls_tokens, cls_token);

    for (int l = 0; l < NL; l++) {
        ln_kernel<<<MTOK, 256>>>(px, DM, ph, ln1w + l * DM, ln1b + l * DM);
        gemm_nt<false><<<dim3(3 * DM / 64, MTOK / 64), 128>>>(
            ph, Wqkv + (long)l * 3 * DM * DM, nullptr, pqkv, 3 * DM, DM);
        attn_kernel<<<dim3(SEQ / 64, NB * NH), 128, ATTN_SMEM_BYTES>>>(log_slopes);
        gemm_nt<true><<<dim3(DM / 64, MTOK / 64), 128>>>(
            po, Wo + (long)l * DM * DM, px, px, DM, DM);
        ln_kernel<<<MTOK, 256>>>(px, DM, ph, ln2w + l * DM, ln2b + l * DM);
        gemm_gateup<<<dim3(DFF / 64, MTOK / 64), 128>>>(
            ph, Wg + (long)l * DFF * DM, Wu + (long)l * DFF * DM, pact);
        gemm_nt<true><<<dim3(DM / 64, MTOK / 64), 128>>>(
            pact, Wd + (long)l * DM * DFF, px, px, DM, DFF);
    }

    ln_kernel<<<NB, 256>>>(px, SEQ * DM, out, finw, finb);
}

// round 9
// speedup vs baseline: 1.0004x; 1.0004x over previous
#include <cuda_runtime.h>
#include <math.h>

#define NL 6
#define NH 16
#define DM 768
#define DFF 3072
#define NB 4
#define NTOKS 1023
#define SEQ 1024
#define HDIM 48
#define MTOK (NB * SEQ)      // 4096 tokens
#define LN_EPS 1e-5f

typedef unsigned long long u64;

// ---------------- packed f32x2 helpers (FFMA2 path, PTX-only) ----------------
__device__ __forceinline__ u64 dup2(float x) {
    u64 r; asm("mov.b64 %0, {%1, %1};" : "=l"(r) : "f"(x)); return r;
}
__device__ __forceinline__ u64 pk2(float lo, float hi) {
    u64 r; asm("mov.b64 %0, {%1, %2};" : "=l"(r) : "f"(lo), "f"(hi)); return r;
}
__device__ __forceinline__ void upk2(u64 v, float& lo, float& hi) {
    asm("mov.b64 {%0, %1}, %2;" : "=f"(lo), "=f"(hi) : "l"(v));
}
__device__ __forceinline__ void fma2(u64& d, u64 a, u64 b) {
    asm("fma.rn.f32x2 %0, %1, %2, %3;" : "=l"(d) : "l"(a), "l"(b), "l"(d));
}
__device__ __forceinline__ u64 mul2(u64 a, u64 b) {
    u64 d; asm("mul.rn.f32x2 %0, %1, %2;" : "=l"(d) : "l"(a), "l"(b)); return d;
}

// ---------------- scratch (device globals; no allocation APIs) ----------------
__device__ float g_x[MTOK * DM];          // residual stream
__device__ float g_h[MTOK * DM];          // LN output
__device__ float g_qkv[MTOK * 3 * DM];    // qkv projections
__device__ float g_o[MTOK * DM];          // attention output
__device__ float g_act[MTOK * DFF];       // silu(gate)*up

// ---------------- embed: x = concat(cls_token, cls_tokens) ----------------
__global__ void embed_kernel(const float* __restrict__ cls_tokens,
                             const float* __restrict__ cls_token) {
    int idx = blockIdx.x * blockDim.x + threadIdx.x;
    if (idx >= MTOK * DM) return;
    int d = idx % DM;
    int tok = idx / DM;
    int b = tok / SEQ, s = tok % SEQ;
    g_x[idx] = (s == 0) ? cls_token[d]
                        : cls_tokens[(b * NTOKS + (s - 1)) * DM + d];
}

// ---------------- layernorm: one block per row, 256 threads ----------------
__global__ void ln_kernel(const float* __restrict__ src, int src_row_stride,
                          float* __restrict__ dst,
                          const float* __restrict__ w,
                          const float* __restrict__ bias) {
    int row = blockIdx.x;
    const float* xp = src + (long)row * src_row_stride;
    float* yp = dst + (long)row * DM;
    int tid = threadIdx.x;  // 256
    float v0 = xp[tid], v1 = xp[tid + 256], v2 = xp[tid + 512];
    float s1 = v0 + v1 + v2;
    float s2 = v0 * v0 + v1 * v1 + v2 * v2;
#pragma unroll
    for (int off = 16; off > 0; off >>= 1) {
        s1 += __shfl_xor_sync(0xffffffff, s1, off);
        s2 += __shfl_xor_sync(0xffffffff, s2, off);
    }
    __shared__ float sm1[8], sm2[8];
    int wid = tid >> 5, lid = tid & 31;
    if (lid == 0) { sm1[wid] = s1; sm2[wid] = s2; }
    __syncthreads();
    if (wid == 0) {
        float t1 = (lid < 8) ? sm1[lid] : 0.f;
        float t2 = (lid < 8) ? sm2[lid] : 0.f;
#pragma unroll
        for (int off = 4; off > 0; off >>= 1) {
            t1 += __shfl_xor_sync(0xffffffff, t1, off);
            t2 += __shfl_xor_sync(0xffffffff, t2, off);
        }
        if (lid == 0) { sm1[0] = t1; sm2[0] = t2; }
    }
    __syncthreads();
    float mean = sm1[0] * (1.f / DM);
    float var = sm2[0] * (1.f / DM) - mean * mean;
    float rstd = rsqrtf(var + LN_EPS);
    yp[tid]       = (v0 - mean) * rstd * w[tid]       + bias[tid];
    yp[tid + 256] = (v1 - mean) * rstd * w[tid + 256] + bias[tid + 256];
    yp[tid + 512] = (v2 - mean) * rstd * w[tid + 512] + bias[tid + 512];
}

// ---------------- GEMM (NT): C[m,n] = sum_k A[m,k]*B[n,k] (+ residual) -------
// 64x64x16 tile, 128 threads, per-thread 4x8 micro-tile on packed f32x2 accs.
template <bool RESID>
__global__ void __launch_bounds__(128)
gemm_nt(const float* __restrict__ A, const float* __restrict__ Bm,
        const float* __restrict__ Rin, float* __restrict__ Cm,
        int Ndim, int Kdim) {
    __shared__ float As[16][64];
    __shared__ float Bs[16][64];
    int tid = threadIdx.x;
    int m0 = blockIdx.y * 64, n0 = blockIdx.x * 64;
    int a = tid >> 3;   // 0..15 : row group
    int b8 = tid & 7;   // 0..7  : col group
    u64 acc[4][4];      // [row][col-pair]: pairs {b8*4+0,1},{+2,3},{32+b8*4+0,1},{+2,3}
#pragma unroll
    for (int r = 0; r < 4; r++)
#pragma unroll
        for (int c = 0; c < 4; c++) acc[r][c] = 0ull;

    const float* Ab = A + (long)m0 * Kdim;
    const float* Bb = Bm + (long)n0 * Kdim;

    for (int k0 = 0; k0 < Kdim; k0 += 16) {
#pragma unroll
        for (int i = 0; i < 2; i++) {
            int idx = tid * 2 + i;        // 0..255
            int row = idx >> 2;           // 0..63
            int kk = (idx & 3) * 4;       // 0,4,8,12
            float4 va = *(const float4*)(Ab + (long)row * Kdim + k0 + kk);
            As[kk + 0][row] = va.x; As[kk + 1][row] = va.y;
            As[kk + 2][row] = va.z; As[kk + 3][row] = va.w;
            float4 vb = *(const float4*)(Bb + (long)row * Kdim + k0 + kk);
            Bs[kk + 0][row] = vb.x; Bs[kk + 1][row] = vb.y;
            Bs[kk + 2][row] = vb.z; Bs[kk + 3][row] = vb.w;
        }
        __syncthreads();
#pragma unroll
        for (int k = 0; k < 16; k++) {
            float4 av = *(const float4*)&As[k][a * 4];
            const u64* bq0 = (const u64*)&Bs[k][b8 * 4];
            const u64* bq1 = (const u64*)&Bs[k][32 + b8 * 4];
            u64 b2[4] = {bq0[0], bq0[1], bq1[0], bq1[1]};
            u64 a2[4] = {dup2(av.x), dup2(av.y), dup2(av.z), dup2(av.w)};
#pragma unroll
            for (int r = 0; r < 4; r++)
#pragma unroll
                for (int c = 0; c < 4; c++) fma2(acc[r][c], a2[r], b2[c]);
        }
        __syncthreads();
    }
#pragma unroll
    for (int r = 0; r < 4; r++) {
        int m = m0 + a * 4 + r;
        float* crow = Cm + (long)m * Ndim + n0;
        float o[8];
        upk2(acc[r][0], o[0], o[1]); upk2(acc[r][1], o[2], o[3]);
        upk2(acc[r][2], o[4], o[5]); upk2(acc[r][3], o[6], o[7]);
#pragma unroll
        for (int half = 0; half < 2; half++) {
            int coff = half * 32 + b8 * 4;
            float4 v;
            v.x = o[half * 4 + 0]; v.y = o[half * 4 + 1];
            v.z = o[half * 4 + 2]; v.w = o[half * 4 + 3];
            if (RESID) {
                float4 rv = *(const float4*)(Rin + (long)m * Ndim + n0 + coff);
                v.x += rv.x; v.y += rv.y; v.z += rv.z; v.w += rv.w;
            }
            *(float4*)(crow + coff) = v;
        }
    }
}

// ---------------- fused gate/up GEMM + SiLU ----------------
__global__ void __launch_bounds__(128)
gemm_gateup(const float* __restrict__ Hm, const float* __restrict__ Wg,
            const float* __restrict__ Wu, float* __restrict__ Act) {
    __shared__ float As[16][64];
    __shared__ float Gs[16][64];
    __shared__ float Us[16][64];
    int tid = threadIdx.x;
    int m0 = blockIdx.y * 64, n0 = blockIdx.x * 64;
    int a = tid >> 3, b8 = tid & 7;
    u64 ag[4][4], au[4][4];
#pragma unroll
    for (int r = 0; r < 4; r++)
#pragma unroll
        for (int c = 0; c < 4; c++) { ag[r][c] = 0ull; au[r][c] = 0ull; }

    const float* Ab = Hm + (long)m0 * DM;
    const float* Gb = Wg + (long)n0 * DM;
    const float* Ub = Wu + (long)n0 * DM;

    for (int k0 = 0; k0 < DM; k0 += 16) {
#pragma unroll
        for (int i = 0; i < 2; i++) {
            int idx = tid * 2 + i;
            int row = idx >> 2;
            int kk = (idx & 3) * 4;
            float4 va = *(const float4*)(Ab + (long)row * DM + k0 + kk);
            As[kk + 0][row] = va.x; As[kk + 1][row] = va.y;
            As[kk + 2][row] = va.z; As[kk + 3][row] = va.w;
            float4 vg = *(const float4*)(Gb + (long)row * DM + k0 + kk);
            Gs[kk + 0][row] = vg.x; Gs[kk + 1][row] = vg.y;
            Gs[kk + 2][row] = vg.z; Gs[kk + 3][row] = vg.w;
            float4 vu = *(const float4*)(Ub + (long)row * DM + k0 + kk);
            Us[kk + 0][row] = vu.x; Us[kk + 1][row] = vu.y;
            Us[kk + 2][row] = vu.z; Us[kk + 3][row] = vu.w;
        }
        __syncthreads();
#pragma unroll
        for (int k = 0; k < 16; k++) {
            float4 av = *(const float4*)&As[k][a * 4];
            const u64* gq0 = (const u64*)&Gs[k][b8 * 4];
            const u64* gq1 = (const u64*)&Gs[k][32 + b8 * 4];
            const u64* uq0 = (const u64*)&Us[k][b8 * 4];
            const u64* uq1 = (const u64*)&Us[k][32 + b8 * 4];
            u64 g2[4] = {gq0[0], gq0[1], gq1[0], gq1[1]};
            u64 u2[4] = {uq0[0], uq0[1], uq1[0], uq1[1]};
            u64 a2[4] = {dup2(av.x), dup2(av.y), dup2(av.z), dup2(av.w)};
#pragma unroll
            for (int r = 0; r < 4; r++)
#pragma unroll
                for (int c = 0; c < 4; c++) {
                    fma2(ag[r][c], a2[r], g2[c]);
                    fma2(au[r][c], a2[r], u2[c]);
                }
        }
        __syncthreads();
    }
#pragma unroll
    for (int r = 0; r < 4; r++) {
        int m = m0 + a * 4 + r;
        float* crow = Act + (long)m * DFF + n0;
        float go[8], uo[8];
        upk2(ag[r][0], go[0], go[1]); upk2(ag[r][1], go[2], go[3]);
        upk2(ag[r][2], go[4], go[5]); upk2(ag[r][3], go[6], go[7]);
        upk2(au[r][0], uo[0], uo[1]); upk2(au[r][1], uo[2], uo[3]);
        upk2(au[r][2], uo[4], uo[5]); upk2(au[r][3], uo[6], uo[7]);
#pragma unroll
        for (int half = 0; half < 2; half++) {
            int coff = half * 32 + b8 * 4;
            float4 o;
#pragma unroll
            for (int c = 0; c < 4; c++) {
                float g = go[half * 4 + c];
                float u = uo[half * 4 + c];
                float s = g / (1.f + __expf(-g));  // silu
                ((float*)&o)[c] = s * u;
            }
            *(float4*)(crow + coff) = o;
        }
    }
}

// ---------------- flash attention (fp32, online softmax, ALiBi) ----------------
// grid: (SEQ/64 q-tiles, B*H). 128 threads. 64x64 score tile, HD=48.
// Qs/Ks rows padded to 49; Vs rows padded to 50 (8B alignment for u64 loads).
#define ATTN_SMEM_FLOATS 13824
#define ATTN_SMEM_BYTES (ATTN_SMEM_FLOATS * 4)

__global__ void __launch_bounds__(128)
attn_kernel(const float* __restrict__ log_slopes) {
    extern __shared__ float sm[];
    float (*Qs)[49] = (float(*)[49])sm;              // 64x49
    float (*Ks)[49] = (float(*)[49])(sm + 3136);     // 64x49
    float (*Vs)[50] = (float(*)[50])(sm + 6272);     // 64x50
    float (*Ps)[65] = (float(*)[65])(sm + 9472);     // 64x65
    float* mrow = sm + 13632;
    float* lrow = sm + 13696;
    float* crow = sm + 13760;

    int qt = blockIdx.x;
    int bh = blockIdx.y;
    int b = bh >> 4, h = bh & 15;
    int tid = threadIdx.x;
    int a = tid >> 3;   // 0..15
    int b8 = tid & 7;   // 0..7
    float slope = expf(log_slopes[h]);
    const float scale = 0.14433756729740643f;  // 1/sqrt(48)
    int q0 = qt * 64;
    const float* qkvb = g_qkv + (long)b * SEQ * (3 * DM);

    // load Q tile
    for (int i = tid; i < 64 * 12; i += 128) {
        int r = i / 12, c4 = (i % 12) * 4;
        float4 v = *(const float4*)(qkvb + (long)(q0 + r) * (3 * DM) + h * HDIM + c4);
        Qs[r][c4 + 0] = v.x; Qs[r][c4 + 1] = v.y;
        Qs[r][c4 + 2] = v.z; Qs[r][c4 + 3] = v.w;
    }
    if (tid < 64) { mrow[tid] = -1e30f; lrow[tid] = 0.f; }
    u64 o2[4][3];
#pragma unroll
    for (int r = 0; r < 4; r++)
#pragma unroll
        for (int c = 0; c < 3; c++) o2[r][c] = 0ull;
    __syncthreads();

    for (int kt = 0; kt < SEQ; kt += 64) {
        // load K, V tiles
        for (int i = tid; i < 64 * 12; i += 128) {
            int r = i / 12, c4 = (i % 12) * 4;
            const float* kp = qkvb + (long)(kt + r) * (3 * DM) + DM + h * HDIM + c4;
            float4 kv = *(const float4*)kp;
            Ks[r][c4 + 0] = kv.x; Ks[r][c4 + 1] = kv.y;
            Ks[r][c4 + 2] = kv.z; Ks[r][c4 + 3] = kv.w;
            float4 vv = *(const float4*)(kp + DM);
            Vs[r][c4 + 0] = vv.x; Vs[r][c4 + 1] = vv.y;
            Vs[r][c4 + 2] = vv.z; Vs[r][c4 + 3] = vv.w;
        }
        __syncthreads();

        // scores: 64x64 = (16x8 threads) x (4x8 micro-tile), packed f32x2
        u64 s2[4][4];
#pragma unroll
        for (int r = 0; r < 4; r++)
#pragma unroll
            for (int c = 0; c < 4; c++) s2[r][c] = 0ull;
#pragma unroll 4
        for (int k = 0; k < HDIM; k++) {
            u64 a2[4] = {dup2(Qs[a * 4 + 0][k]), dup2(Qs[a * 4 + 1][k]),
                         dup2(Qs[a * 4 + 2][k]), dup2(Qs[a * 4 + 3][k])};
            u64 b2[4] = {pk2(Ks[b8 * 8 + 0][k], Ks[b8 * 8 + 1][k]),
                         pk2(Ks[b8 * 8 + 2][k], Ks[b8 * 8 + 3][k]),
                         pk2(Ks[b8 * 8 + 4][k], Ks[b8 * 8 + 5][k]),
                         pk2(Ks[b8 * 8 + 6][k], Ks[b8 * 8 + 7][k])};
#pragma unroll
            for (int r = 0; r < 4; r++)
#pragma unroll
                for (int c = 0; c < 4; c++) fma2(s2[r][c], a2[r], b2[c]);
        }
#pragma unroll
        for (int r = 0; r < 4; r++) {
            int qi = q0 + a * 4 + r;
#pragma unroll
            for (int c = 0; c < 4; c++) {
                float p0, p1;
                upk2(s2[r][c], p0, p1);
                int kj = kt + b8 * 8 + 2 * c;
                Ps[a * 4 + r][b8 * 8 + 2 * c] =
                    p0 * scale - slope * fabsf((float)(qi - kj));
                Ps[a * 4 + r][b8 * 8 + 2 * c + 1] =
                    p1 * scale - slope * fabsf((float)(qi - kj - 1));
            }
        }
        __syncthreads();

        // online softmax, one thread per row
        if (tid < 64) {
            int row = tid;
            float mold = mrow[row];
            float mx = mold;
#pragma unroll 8
            for (int j = 0; j < 64; j++) mx = fmaxf(mx, Ps[row][j]);
            float corr = __expf(mold - mx);
            float sum = 0.f;
#pragma unroll 8
            for (int j = 0; j < 64; j++) {
                float p = __expf(Ps[row][j] - mx);
                Ps[row][j] = p;
                sum += p;
            }
            lrow[row] = lrow[row] * corr + sum;
            mrow[row] = mx;
            crow[row] = corr;
        }
        __syncthreads();

        // o = o*corr + P @ V : per-thread 4 rows x 6 cols (3 packed pairs)
#pragma unroll
        for (int r = 0; r < 4; r++) {
            u64 cd = dup2(crow[a * 4 + r]);
#pragma unroll
            for (int c = 0; c < 3; c++) o2[r][c] = mul2(o2[r][c], cd);
        }
#pragma unroll 8
        for (int j = 0; j < 64; j++) {
            const u64* vp = (const u64*)&Vs[j][b8 * 6];
            u64 v2[3] = {vp[0], vp[1], vp[2]};
            u64 p2[4] = {dup2(Ps[a * 4 + 0][j]), dup2(Ps[a * 4 + 1][j]),
                         dup2(Ps[a * 4 + 2][j]), dup2(Ps[a * 4 + 3][j])};
#pragma unroll
            for (int r = 0; r < 4; r++)
#pragma unroll
                for (int c = 0; c < 3; c++) fma2(o2[r][c], p2[r], v2[c]);
        }
        __syncthreads();
    }

    // normalize + write: o[row][col] layout (b, s, h*HD + col)
#pragma unroll
    for (int r = 0; r < 4; r++) {
        int row = a * 4 + r;
        float inv = 1.f / lrow[row];
        float* op = g_o + (long)(b * SEQ + q0 + row) * DM + h * HDIM + b8 * 6;
#pragma unroll
        for (int c = 0; c < 3; c++) {
            float lo, hi;
            upk2(o2[r][c], lo, hi);
            float2 st; st.x = lo * inv; st.y = hi * inv;
            *(float2*)(op + 2 * c) = st;
        }
    }
}

// ---------------- launch ----------------
extern "C" void kernel_launch(void* const* d_in, const int* in_sizes, int n_in,
                              void* d_out, int out_size) {
    (void)in_sizes; (void)n_in; (void)out_size;
    const float* cls_tokens = (const float*)d_in[0];
    const float* cls_token  = (const float*)d_in[1];
    const float* log_slopes = (const float*)d_in[2];
    const float* Wqkv = (const float*)d_in[3];
    const float* Wo   = (const float*)d_in[4];
    const float* Wg   = (const float*)d_in[5];
    const float* Wu   = (const float*)d_in[6];
    const float* Wd   = (const float*)d_in[7];
    const float* ln1w = (const float*)d_in[8];
    const float* ln1b = (const float*)d_in[9];
    const float* ln2w = (const float*)d_in[10];
    const float* ln2b = (const float*)d_in[11];
    const float* finw = (const float*)d_in[12];
    const float* finb = (const float*)d_in[13];
    float* out = (float*)d_out;

    float *px, *ph, *pqkv, *po, *pact;
    cudaGetSymbolAddress((void**)&px, g_x);
    cudaGetSymbolAddress((void**)&ph, g_h);
    cudaGetSymbolAddress((void**)&pqkv, g_qkv);
    cudaGetSymbolAddress((void**)&po, g_o);
    cudaGetSymbolAddress((void**)&pact, g_act);

    cudaFuncSetAttribute(attn_kernel,
                         cudaFuncAttributeMaxDynamicSharedMemorySize,
                         ATTN_SMEM_BYTES);

    embed_kernel<<<(MTOK * DM + 255) / 256, 256>>>(cls_tokens, cls_token);

    for (int l = 0; l < NL; l++) {
        ln_kernel<<<MTOK, 256>>>(px, DM, ph, ln1w + l * DM, ln1b + l * DM);
        gemm_nt<false><<<dim3(3 * DM / 64, MTOK / 64), 128>>>(
            ph, Wqkv + (long)l * 3 * DM * DM, nullptr, pqkv, 3 * DM, DM);
        attn_kernel<<<dim3(SEQ / 64, NB * NH), 128, ATTN_SMEM_BYTES>>>(log_slopes);
        gemm_nt<true><<<dim3(DM / 64, MTOK / 64), 128>>>(
            po, Wo + (long)l * DM * DM, px, px, DM, DM);
        ln_kernel<<<MTOK, 256>>>(px, DM, ph, ln2w + l * DM, ln2b + l * DM);
        gemm_gateup<<<dim3(DFF / 64, MTOK / 64), 128>>>(
            ph, Wg + (long)l * DFF * DM, Wu + (long)l * DFF * DM, pact);
        gemm_nt<true><<<dim3(DM / 64, MTOK / 64), 128>>>(
            pact, Wd + (long)l * DM * DFF, px, px, DM, DFF);
    }

    ln_kernel<<<NB, 256>>>(px, SEQ * DM, out, finw, finb);
}

// round 11
// speedup vs baseline: 1.0013x; 1.0010x over previous
#include <cuda_runtime.h>
#include <math.h>
#include <stdint.h>

#define NL 6
#define NH 16
#define DM 768
#define DFF 3072
#define NB 4
#define NTOKS 1023
#define SEQ 1024
#define HDIM 48
#define MTOK (NB * SEQ)      // 4096 tokens
#define LN_EPS 1e-5f

// ---------------- scratch (device globals; no allocation APIs) ----------------
__device__ float g_x[MTOK * DM];          // residual stream
__device__ float g_h[MTOK * DM];          // LN output
__device__ float g_qkv[MTOK * 3 * DM];    // qkv projections
__device__ float g_o[MTOK * DM];          // attention output
__device__ float g_act[MTOK * DFF];       // gate -> silu(gate)*up
__device__ float g_up[MTOK * DFF];        // up

// ---------------- tf32 helpers ----------------
__device__ __forceinline__ void tf32_split(float x, float& hi, float& lo) {
    uint32_t hb;
    asm("cvt.rna.tf32.f32 %0, %1;" : "=r"(hb) : "f"(x));
    hi = __uint_as_float(hb);
    float l = x - hi;
    uint32_t lb;
    asm("cvt.rna.tf32.f32 %0, %1;" : "=r"(lb) : "f"(l));
    lo = __uint_as_float(lb);
}

__device__ __forceinline__ void mma_tf32(float* d, const uint32_t* a, const uint32_t* b) {
    asm volatile(
        "mma.sync.aligned.m16n8k8.row.col.f32.tf32.tf32.f32 "
        "{%0,%1,%2,%3}, {%4,%5,%6,%7}, {%8,%9}, {%0,%1,%2,%3};"
        : "+f"(d[0]), "+f"(d[1]), "+f"(d[2]), "+f"(d[3])
        : "r"(a[0]), "r"(a[1]), "r"(a[2]), "r"(a[3]), "r"(b[0]), "r"(b[1]));
}

// ---------------- embed: x = concat(cls_token, cls_tokens) ----------------
__global__ void embed_kernel(const float* __restrict__ cls_tokens,
                             const float* __restrict__ cls_token) {
    int idx = blockIdx.x * blockDim.x + threadIdx.x;
    if (idx >= MTOK * DM) return;
    int d = idx % DM;
    int tok = idx / DM;
    int b = tok / SEQ, s = tok % SEQ;
    g_x[idx] = (s == 0) ? cls_token[d]
                        : cls_tokens[(b * NTOKS + (s - 1)) * DM + d];
}

// ---------------- layernorm: one block per row, 256 threads ----------------
__global__ void ln_kernel(const float* __restrict__ src, int src_row_stride,
                          float* __restrict__ dst,
                          const float* __restrict__ w,
                          const float* __restrict__ bias) {
    int row = blockIdx.x;
    const float* xp = src + (long)row * src_row_stride;
    float* yp = dst + (long)row * DM;
    int tid = threadIdx.x;  // 256
    float v0 = xp[tid], v1 = xp[tid + 256], v2 = xp[tid + 512];
    float s1 = v0 + v1 + v2;
    float s2 = v0 * v0 + v1 * v1 + v2 * v2;
#pragma unroll
    for (int off = 16; off > 0; off >>= 1) {
        s1 += __shfl_xor_sync(0xffffffff, s1, off);
        s2 += __shfl_xor_sync(0xffffffff, s2, off);
    }
    __shared__ float sm1[8], sm2[8];
    int wid = tid >> 5, lid = tid & 31;
    if (lid == 0) { sm1[wid] = s1; sm2[wid] = s2; }
    __syncthreads();
    if (wid == 0) {
        float t1 = (lid < 8) ? sm1[lid] : 0.f;
        float t2 = (lid < 8) ? sm2[lid] : 0.f;
#pragma unroll
        for (int off = 4; off > 0; off >>= 1) {
            t1 += __shfl_xor_sync(0xffffffff, t1, off);
            t2 += __shfl_xor_sync(0xffffffff, t2, off);
        }
        if (lid == 0) { sm1[0] = t1; sm2[0] = t2; }
    }
    __syncthreads();
    float mean = sm1[0] * (1.f / DM);
    float var = sm2[0] * (1.f / DM) - mean * mean;
    float rstd = rsqrtf(var + LN_EPS);
    yp[tid]       = (v0 - mean) * rstd * w[tid]       + bias[tid];
    yp[tid + 256] = (v1 - mean) * rstd * w[tid + 256] + bias[tid + 256];
    yp[tid + 512] = (v2 - mean) * rstd * w[tid + 512] + bias[tid + 512];
}

// ---------------- tensor-core GEMM (NT, 3xTF32): C = A @ B^T (+R) ----------
// Block: 128 threads = 4 warps (2x2), tile M64 x N64, K-step 32.
// smem: hi/lo split tiles, row stride 36 (bank = 4*row + k = lane, conflict-free).
#define KSTEP 32
#define LDT 36

template <bool RESID>
__global__ void __launch_bounds__(128)
gemm_nt_tc(const float* __restrict__ A, const float* __restrict__ Bm,
           const float* __restrict__ Rin, float* __restrict__ Cm,
           int Ndim, int Kdim) {
    __shared__ float Ah[64][LDT], Al[64][LDT];
    __shared__ float Bh[64][LDT], Bl[64][LDT];
    int tid = threadIdx.x;
    int lane = tid & 31, warp = tid >> 5;
    int wm = warp & 1, wn = warp >> 1;      // 2x2 warp grid
    int m0 = blockIdx.y * 64, n0 = blockIdx.x * 64;

    float acc[2][4][4];                      // [m16-tile][n8-tile][4]
#pragma unroll
    for (int mt = 0; mt < 2; mt++)
#pragma unroll
        for (int nt = 0; nt < 4; nt++)
#pragma unroll
            for (int i = 0; i < 4; i++) acc[mt][nt][i] = 0.f;

    const float* Ab = A + (long)m0 * Kdim;
    const float* Bb = Bm + (long)n0 * Kdim;
    int qr = lane >> 2;        // 0..7
    int qc = lane & 3;         // 0..3

    for (int k0 = 0; k0 < Kdim; k0 += KSTEP) {
        // stage + split: 64 rows x 32 k, 512 float4 per operand
#pragma unroll
        for (int i = 0; i < 4; i++) {
            int linear = i * 128 + tid;           // 0..511
            int row = linear >> 3;                // 0..63
            int kg = (linear & 7) * 4;            // 0,4,...,28
            float4 va = *(const float4*)(Ab + (long)row * Kdim + k0 + kg);
            float4 vb = *(const float4*)(Bb + (long)row * Kdim + k0 + kg);
            float h, l;
            tf32_split(va.x, h, l); Ah[row][kg + 0] = h; Al[row][kg + 0] = l;
            tf32_split(va.y, h, l); Ah[row][kg + 1] = h; Al[row][kg + 1] = l;
            tf32_split(va.z, h, l); Ah[row][kg + 2] = h; Al[row][kg + 2] = l;
            tf32_split(va.w, h, l); Ah[row][kg + 3] = h; Al[row][kg + 3] = l;
            tf32_split(vb.x, h, l); Bh[row][kg + 0] = h; Bl[row][kg + 0] = l;
            tf32_split(vb.y, h, l); Bh[row][kg + 1] = h; Bl[row][kg + 1] = l;
            tf32_split(vb.z, h, l); Bh[row][kg + 2] = h; Bl[row][kg + 2] = l;
            tf32_split(vb.w, h, l); Bh[row][kg + 3] = h; Bl[row][kg + 3] = l;
        }
        __syncthreads();

#pragma unroll
        for (int kk = 0; kk < KSTEP; kk += 8) {
            uint32_t ah[2][4], al[2][4], bh[4][2], bl[4][2];
#pragma unroll
            for (int mt = 0; mt < 2; mt++) {
                int rb = wm * 32 + mt * 16 + qr;
                ah[mt][0] = __float_as_uint(Ah[rb][kk + qc]);
                ah[mt][1] = __float_as_uint(Ah[rb + 8][kk + qc]);
                ah[mt][2] = __float_as_uint(Ah[rb][kk + qc + 4]);
                ah[mt][3] = __float_as_uint(Ah[rb + 8][kk + qc + 4]);
                al[mt][0] = __float_as_uint(Al[rb][kk + qc]);
                al[mt][1] = __float_as_uint(Al[rb + 8][kk + qc]);
                al[mt][2] = __float_as_uint(Al[rb][kk + qc + 4]);
                al[mt][3] = __float_as_uint(Al[rb + 8][kk + qc + 4]);
            }
#pragma unroll
            for (int nt = 0; nt < 4; nt++) {
                int nb = wn * 32 + nt * 8 + qr;
                bh[nt][0] = __float_as_uint(Bh[nb][kk + qc]);
                bh[nt][1] = __float_as_uint(Bh[nb][kk + qc + 4]);
                bl[nt][0] = __float_as_uint(Bl[nb][kk + qc]);
                bl[nt][1] = __float_as_uint(Bl[nb][kk + qc + 4]);
            }
#pragma unroll
            for (int mt = 0; mt < 2; mt++)
#pragma unroll
                for (int nt = 0; nt < 4; nt++) {
                    mma_tf32(acc[mt][nt], ah[mt], bh[nt]);
                    mma_tf32(acc[mt][nt], ah[mt], bl[nt]);
                    mma_tf32(acc[mt][nt], al[mt], bh[nt]);
                }
        }
        __syncthreads();
    }

    // epilogue: warp tile 32x32 at (m0+32wm, n0+32wn)
#pragma unroll
    for (int mt = 0; mt < 2; mt++) {
#pragma unroll
        for (int half = 0; half < 2; half++) {
            int m = m0 + wm * 32 + mt * 16 + qr + half * 8;
            float* crow = Cm + (long)m * Ndim + n0 + wn * 32;
            const float* rrow = RESID ? (Rin + (long)m * Ndim + n0 + wn * 32) : nullptr;
#pragma unroll
            for (int nt = 0; nt < 4; nt++) {
                int coff = nt * 8 + 2 * qc;
                float2 v;
                v.x = acc[mt][nt][half * 2 + 0];
                v.y = acc[mt][nt][half * 2 + 1];
                if (RESID) {
                    float2 rv = *(const float2*)(rrow + coff);
                    v.x += rv.x; v.y += rv.y;
                }
                *(float2*)(crow + coff) = v;
            }
        }
    }
}

// ---------------- silu(gate) * up, elementwise ----------------
__global__ void silu_mul_kernel() {
    int idx = blockIdx.x * blockDim.x + threadIdx.x;
    if (idx >= MTOK * DFF / 4) return;
    float4 g = ((const float4*)g_act)[idx];
    float4 u = ((const float4*)g_up)[idx];
    float4 o;
    o.x = g.x / (1.f + __expf(-g.x)) * u.x;
    o.y = g.y / (1.f + __expf(-g.y)) * u.y;
    o.z = g.z / (1.f + __expf(-g.z)) * u.z;
    o.w = g.w / (1.f + __expf(-g.w)) * u.w;
    ((float4*)g_act)[idx] = o;
}

// ---------------- flash attention (fp32, online softmax, ALiBi) ----------------
// grid: (SEQ/64 q-tiles, B*H). 128 threads. 64x64 score tile, HD=48.
#define ATTN_SMEM_FLOATS 13760
#define ATTN_SMEM_BYTES (ATTN_SMEM_FLOATS * 4)

__global__ void __launch_bounds__(128)
attn_kernel(const float* __restrict__ log_slopes) {
    extern __shared__ float sm[];
    float (*Qs)[49] = (float(*)[49])sm;             // 64x49
    float (*Ks)[49] = (float(*)[49])(sm + 3136);    // 64x49
    float (*Vs)[49] = (float(*)[49])(sm + 6272);    // 64x49
    float (*Ps)[65] = (float(*)[65])(sm + 9408);    // 64x65
    float* mrow = sm + 13568;
    float* lrow = sm + 13632;
    float* crow = sm + 13696;

    int qt = blockIdx.x;
    int bh = blockIdx.y;
    int b = bh >> 4, h = bh & 15;
    int tid = threadIdx.x;
    int a = tid >> 3;   // 0..15
    int b8 = tid & 7;   // 0..7
    float slope = expf(log_slopes[h]);
    const float scale = 0.14433756729740643f;  // 1/sqrt(48)
    int q0 = qt * 64;
    const float* qkvb = g_qkv + (long)b * SEQ * (3 * DM);

    // load Q tile
    for (int i = tid; i < 64 * 12; i += 128) {
        int r = i / 12, c4 = (i % 12) * 4;
        float4 v = *(const float4*)(qkvb + (long)(q0 + r) * (3 * DM) + h * HDIM + c4);
        Qs[r][c4 + 0] = v.x; Qs[r][c4 + 1] = v.y;
        Qs[r][c4 + 2] = v.z; Qs[r][c4 + 3] = v.w;
    }
    if (tid < 64) { mrow[tid] = -1e30f; lrow[tid] = 0.f; }
    float oacc[4][6];
#pragma unroll
    for (int r = 0; r < 4; r++)
#pragma unroll
        for (int c = 0; c < 6; c++) oacc[r][c] = 0.f;
    __syncthreads();

    for (int kt = 0; kt < SEQ; kt += 64) {
        // load K, V tiles
        for (int i = tid; i < 64 * 12; i += 128) {
            int r = i / 12, c4 = (i % 12) * 4;
            const float* kp = qkvb + (long)(kt + r) * (3 * DM) + DM + h * HDIM + c4;
            float4 kv = *(const float4*)kp;
            Ks[r][c4 + 0] = kv.x; Ks[r][c4 + 1] = kv.y;
            Ks[r][c4 + 2] = kv.z; Ks[r][c4 + 3] = kv.w;
            float4 vv = *(const float4*)(kp + DM);
            Vs[r][c4 + 0] = vv.x; Vs[r][c4 + 1] = vv.y;
            Vs[r][c4 + 2] = vv.z; Vs[r][c4 + 3] = vv.w;
        }
        __syncthreads();

        // scores: 64x64 = (16x8 threads) x (4x8 micro-tile)
        float sacc[4][8];
#pragma unroll
        for (int r = 0; r < 4; r++)
#pragma unroll
            for (int c = 0; c < 8; c++) sacc[r][c] = 0.f;
#pragma unroll 8
        for (int k = 0; k < HDIM; k++) {
            float ar[4], br[8];
#pragma unroll
            for (int r = 0; r < 4; r++) ar[r] = Qs[a * 4 + r][k];
#pragma unroll
            for (int c = 0; c < 8; c++) br[c] = Ks[b8 * 8 + c][k];
#pragma unroll
            for (int r = 0; r < 4; r++)
#pragma unroll
                for (int c = 0; c < 8; c++) sacc[r][c] += ar[r] * br[c];
        }
#pragma unroll
        for (int r = 0; r < 4; r++)
#pragma unroll
            for (int c = 0; c < 8; c++) {
                int qi = q0 + a * 4 + r;
                int kj = kt + b8 * 8 + c;
                Ps[a * 4 + r][b8 * 8 + c] =
                    sacc[r][c] * scale - slope * fabsf((float)(qi - kj));
            }
        __syncthreads();

        // online softmax, one thread per row
        if (tid < 64) {
            int row = tid;
            float mold = mrow[row];
            float mx = mold;
#pragma unroll 8
            for (int j = 0; j < 64; j++) mx = fmaxf(mx, Ps[row][j]);
            float corr = __expf(mold - mx);
            float sum = 0.f;
#pragma unroll 8
            for (int j = 0; j < 64; j++) {
                float p = __expf(Ps[row][j] - mx);
                Ps[row][j] = p;
                sum += p;
            }
            lrow[row] = lrow[row] * corr + sum;
            mrow[row] = mx;
            crow[row] = corr;
        }
        __syncthreads();

        // o = o*corr + P @ V : per-thread 4 rows x 6 cols
        float cr[4];
#pragma unroll
        for (int r = 0; r < 4; r++) cr[r] = crow[a * 4 + r];
#pragma unroll
        for (int r = 0; r < 4; r++)
#pragma unroll
            for (int c = 0; c < 6; c++) oacc[r][c] *= cr[r];
#pragma unroll 8
        for (int j = 0; j < 64; j++) {
            float pv[4], vv[6];
#pragma unroll
            for (int r = 0; r < 4; r++) pv[r] = Ps[a * 4 + r][j];
#pragma unroll
            for (int c = 0; c < 6; c++) vv[c] = Vs[j][b8 * 6 + c];
#pragma unroll
            for (int r = 0; r < 4; r++)
#pragma unroll
                for (int c = 0; c < 6; c++) oacc[r][c] += pv[r] * vv[c];
        }
        __syncthreads();
    }

    // normalize + write: o[row][col] layout (b, s, h*HD + col)
#pragma unroll
    for (int r = 0; r < 4; r++) {
        int row = a * 4 + r;
        float inv = 1.f / lrow[row];
#pragma unroll
        for (int c = 0; c < 6; c++) {
            g_o[(long)(b * SEQ + q0 + row) * DM + h * HDIM + b8 * 6 + c] =
                oacc[r][c] * inv;
        }
    }
}

// ---------------- launch ----------------
extern "C" void kernel_launch(void* const* d_in, const int* in_sizes, int n_in,
                              void* d_out, int out_size) {
    (void)in_sizes; (void)n_in; (void)out_size;
    const float* cls_tokens = (const float*)d_in[0];
    const float* cls_token  = (const float*)d_in[1];
    const float* log_slopes = (const float*)d_in[2];
    const float* Wqkv = (const float*)d_in[3];
    const float* Wo   = (const float*)d_in[4];
    const float* Wg   = (const float*)d_in[5];
    const float* Wu   = (const float*)d_in[6];
    const float* Wd   = (const float*)d_in[7];
    const float* ln1w = (const float*)d_in[8];
    const float* ln1b = (const float*)d_in[9];
    const float* ln2w = (const float*)d_in[10];
    const float* ln2b = (const float*)d_in[11];
    const float* finw = (const float*)d_in[12];
    const float* finb = (const float*)d_in[13];
    float* out = (float*)d_out;

    float *px, *ph, *pqkv, *po, *pact, *pup;
    cudaGetSymbolAddress((void**)&px, g_x);
    cudaGetSymbolAddress((void**)&ph, g_h);
    cudaGetSymbolAddress((void**)&pqkv, g_qkv);
    cudaGetSymbolAddress((void**)&po, g_o);
    cudaGetSymbolAddress((void**)&pact, g_act);
    cudaGetSymbolAddress((void**)&pup, g_up);

    cudaFuncSetAttribute(attn_kernel,
                         cudaFuncAttributeMaxDynamicSharedMemorySize,
                         ATTN_SMEM_BYTES);

    embed_kernel<<<(MTOK * DM + 255) / 256, 256>>>(cls_tokens, cls_token);

    for (int l = 0; l < NL; l++) {
        ln_kernel<<<MTOK, 256>>>(px, DM, ph, ln1w + l * DM, ln1b + l * DM);
        gemm_nt_tc<false><<<dim3(3 * DM / 64, MTOK / 64), 128>>>(
            ph, Wqkv + (long)l * 3 * DM * DM, nullptr, pqkv, 3 * DM, DM);
        attn_kernel<<<dim3(SEQ / 64, NB * NH), 128, ATTN_SMEM_BYTES>>>(log_slopes);
        gemm_nt_tc<true><<<dim3(DM / 64, MTOK / 64), 128>>>(
            po, Wo + (long)l * DM * DM, px, px, DM, DM);
        ln_kernel<<<MTOK, 256>>>(px, DM, ph, ln2w + l * DM, ln2b + l * DM);
        gemm_nt_tc<false><<<dim3(DFF / 64, MTOK / 64), 128>>>(
            ph, Wg + (long)l * DFF * DM, nullptr, pact, DFF, DM);
        gemm_nt_tc<false><<<dim3(DFF / 64, MTOK / 64), 128>>>(
            ph, Wu + (long)l * DFF * DM, nullptr, pup, DFF, DM);
        silu_mul_kernel<<<(MTOK * DFF / 4 + 255) / 256, 256>>>();
        gemm_nt_tc<true><<<dim3(DM / 64, MTOK / 64), 128>>>(
            pact, Wd + (long)l * DM * DFF, px, px, DM, DFF);
    }

    ln_kernel<<<NB, 256>>>(px, SEQ * DM, out, finw, finb);
}

// round 13
// speedup vs baseline: 2.1512x; 2.1484x over previous
#include <cuda_runtime.h>
#include <cuda_bf16.h>
#include <math.h>
#include <stdint.h>

#define NL 6
#define NH 16
#define DM 768
#define DFF 3072
#define NB 4
#define NTOKS 1023
#define SEQ 1024
#define HDIM 48
#define MTOK (NB * SEQ)      // 4096 tokens
#define LN_EPS 1e-5f

// weight split layout (elements per layer)
#define WSZ_QKV (3 * DM * DM)
#define WSZ_O   (DM * DM)
#define WSZ_G   (DFF * DM)
#define WSZ_U   (DFF * DM)
#define WSZ_D   (DM * DFF)
#define WSZ_LAYER (WSZ_QKV + WSZ_O + WSZ_G + WSZ_U + WSZ_D)
#define WOFF_QKV 0
#define WOFF_O   (WSZ_QKV)
#define WOFF_G   (WSZ_QKV + WSZ_O)
#define WOFF_U   (WSZ_QKV + WSZ_O + WSZ_G)
#define WOFF_D   (WSZ_QKV + WSZ_O + WSZ_G + WSZ_U)
#define WSZ_ALL  (WSZ_LAYER * NL)

// ---------------- scratch (device globals; no allocation APIs) ----------------
__device__ float g_x[MTOK * DM];          // residual stream
__device__ float g_h[MTOK * DM];          // LN output
__device__ float g_qkv[MTOK * 3 * DM];    // qkv projections
__device__ float g_o[MTOK * DM];          // attention output
__device__ float g_act[MTOK * DFF];       // gate -> silu(gate)*up
__device__ float g_up[MTOK * DFF];        // up
__device__ __nv_bfloat16 g_whi[WSZ_ALL];  // weight hi parts
__device__ __nv_bfloat16 g_wlo[WSZ_ALL];  // weight lo parts
__device__ __nv_bfloat16 g_ahi[MTOK * DFF]; // activation hi (A operand)
__device__ __nv_bfloat16 g_alo[MTOK * DFF]; // activation lo

// ---------------- ptx helpers (sm_80-era only: no tcgen05 on this target) ----
__device__ __forceinline__ uint32_t smem_u32(const void* p) {
    uint32_t a;
    asm("{ .reg .u64 t; cvta.to.shared.u64 t, %1; cvt.u32.u64 %0, t; }"
        : "=r"(a) : "l"(p));
    return a;
}
__device__ __forceinline__ void ldsm_x4(uint32_t* r, uint32_t addr) {
    asm volatile("ldmatrix.sync.aligned.m8n8.x4.shared.b16 {%0,%1,%2,%3}, [%4];"
                 : "=r"(r[0]), "=r"(r[1]), "=r"(r[2]), "=r"(r[3]) : "r"(addr));
}
__device__ __forceinline__ void mma_bf16(float* d, const uint32_t* a,
                                         const uint32_t* b) {
    asm volatile(
        "mma.sync.aligned.m16n8k16.row.col.f32.bf16.bf16.f32 "
        "{%0,%1,%2,%3}, {%4,%5,%6,%7}, {%8,%9}, {%0,%1,%2,%3};"
        : "+f"(d[0]), "+f"(d[1]), "+f"(d[2]), "+f"(d[3])
        : "r"(a[0]), "r"(a[1]), "r"(a[2]), "r"(a[3]), "r"(b[0]), "r"(b[1]));
}
__device__ __forceinline__ void cp16(uint32_t smem, const void* g) {
    asm volatile("cp.async.ca.shared.global [%0], [%1], 16;"
                 :: "r"(smem), "l"(g) : "memory");
}
__device__ __forceinline__ void cp_commit() {
    asm volatile("cp.async.commit_group;" ::: "memory");
}
template <int N>
__device__ __forceinline__ void cp_wait() {
    asm volatile("cp.async.wait_group %0;" :: "n"(N) : "memory");
}

// ---------------- bf16 hi/lo split ----------------
__global__ void split_kernel(const float* __restrict__ src,
                             __nv_bfloat16* __restrict__ hi,
                             __nv_bfloat16* __restrict__ lo, int n4) {
    int i = blockIdx.x * blockDim.x + threadIdx.x;
    if (i >= n4) return;
    float4 v = ((const float4*)src)[i];
    __nv_bfloat16 h0 = __float2bfloat16(v.x);
    __nv_bfloat16 h1 = __float2bfloat16(v.y);
    __nv_bfloat16 h2 = __float2bfloat16(v.z);
    __nv_bfloat16 h3 = __float2bfloat16(v.w);
    __nv_bfloat16 l0 = __float2bfloat16(v.x - __bfloat162float(h0));
    __nv_bfloat16 l1 = __float2bfloat16(v.y - __bfloat162float(h1));
    __nv_bfloat16 l2 = __float2bfloat16(v.z - __bfloat162float(h2));
    __nv_bfloat16 l3 = __float2bfloat16(v.w - __bfloat162float(h3));
    __nv_bfloat162* hp = (__nv_bfloat162*)hi;
    __nv_bfloat162* lp = (__nv_bfloat162*)lo;
    hp[2 * i]     = __nv_bfloat162(h0, h1);
    hp[2 * i + 1] = __nv_bfloat162(h2, h3);
    lp[2 * i]     = __nv_bfloat162(l0, l1);
    lp[2 * i + 1] = __nv_bfloat162(l2, l3);
}

// ---------------- embed ----------------
__global__ void embed_kernel(const float* __restrict__ cls_tokens,
                             const float* __restrict__ cls_token) {
    int idx = blockIdx.x * blockDim.x + threadIdx.x;
    if (idx >= MTOK * DM) return;
    int d = idx % DM;
    int tok = idx / DM;
    int b = tok / SEQ, s = tok % SEQ;
    g_x[idx] = (s == 0) ? cls_token[d]
                        : cls_tokens[(b * NTOKS + (s - 1)) * DM + d];
}

// ---------------- layernorm ----------------
__global__ void ln_kernel(const float* __restrict__ src, int src_row_stride,
                          float* __restrict__ dst,
                          const float* __restrict__ w,
                          const float* __restrict__ bias) {
    int row = blockIdx.x;
    const float* xp = src + (long)row * src_row_stride;
    float* yp = dst + (long)row * DM;
    int tid = threadIdx.x;  // 256
    float v0 = xp[tid], v1 = xp[tid + 256], v2 = xp[tid + 512];
    float s1 = v0 + v1 + v2;
    float s2 = v0 * v0 + v1 * v1 + v2 * v2;
#pragma unroll
    for (int off = 16; off > 0; off >>= 1) {
        s1 += __shfl_xor_sync(0xffffffff, s1, off);
        s2 += __shfl_xor_sync(0xffffffff, s2, off);
    }
    __shared__ float sm1[8], sm2[8];
    int wid = tid >> 5, lid = tid & 31;
    if (lid == 0) { sm1[wid] = s1; sm2[wid] = s2; }
    __syncthreads();
    if (wid == 0) {
        float t1 = (lid < 8) ? sm1[lid] : 0.f;
        float t2 = (lid < 8) ? sm2[lid] : 0.f;
#pragma unroll
        for (int off = 4; off > 0; off >>= 1) {
            t1 += __shfl_xor_sync(0xffffffff, t1, off);
            t2 += __shfl_xor_sync(0xffffffff, t2, off);
        }
        if (lid == 0) { sm1[0] = t1; sm2[0] = t2; }
    }
    __syncthreads();
    float mean = sm1[0] * (1.f / DM);
    float var = sm2[0] * (1.f / DM) - mean * mean;
    float rstd = rsqrtf(var + LN_EPS);
    yp[tid]       = (v0 - mean) * rstd * w[tid]       + bias[tid];
    yp[tid + 256] = (v1 - mean) * rstd * w[tid + 256] + bias[tid + 256];
    yp[tid + 512] = (v2 - mean) * rstd * w[tid + 512] + bias[tid + 512];
}

// ---------------- bf16 tensor-core GEMM (NT): C = A @ B^T (+R) ---------------
// Tile M128 x N128, 256 threads = 8 warps (2x4); warp tile 64x32.
// K chunks of 64, double-buffered cp.async. 3-term hi/lo compensation.
// smem per buffer 64KB: Ahi 16K | Alo 16K | Bhi 16K | Blo 16K. Rows = 128B,
// 16B-unit XOR swizzle (kq ^ (row&7)) for conflict-free LDSM + cp.async stores.
#define GB_BUF 65536
#define GB_SMEM (2 * GB_BUF)

__device__ __forceinline__ void stage_gb(
    uint32_t sb, int buf,
    const __nv_bfloat16* __restrict__ Ahi, const __nv_bfloat16* __restrict__ Alo,
    const __nv_bfloat16* __restrict__ Bhi, const __nv_bfloat16* __restrict__ Blo,
    int m0, int n0, int Kdim, int c, int tid) {
    uint32_t base = sb + buf * GB_BUF;
    size_t ka = (size_t)m0 * Kdim + c * 64;
    size_t kb = (size_t)n0 * Kdim + c * 64;
#pragma unroll
    for (int i = 0; i < 4; i++) {
        int u = i * 256 + tid;               // 0..1023
        int r = u >> 3, kq = u & 7;
        uint32_t d = base + r * 128 + ((kq ^ (r & 7)) << 4);
        size_t sa = ka + (size_t)r * Kdim + kq * 8;
        size_t sbn = kb + (size_t)r * Kdim + kq * 8;
        cp16(d,                 Ahi + sa);
        cp16(d + 16384,         Alo + sa);
        cp16(d + 32768,         Bhi + sbn);
        cp16(d + 49152,         Blo + sbn);
    }
}

template <bool RESID>
__global__ void __launch_bounds__(256, 1)
gemm_bf16(const __nv_bfloat16* __restrict__ Ahi, const __nv_bfloat16* __restrict__ Alo,
          const __nv_bfloat16* __restrict__ Bhi, const __nv_bfloat16* __restrict__ Blo,
          const float* __restrict__ Rin, float* __restrict__ Cm,
          int Ndim, int Kdim) {
    extern __shared__ char smem[];
    uint32_t sb = smem_u32(smem);
    int tid = threadIdx.x;
    int lane = tid & 31, warp = tid >> 5;
    int wm = warp & 1, wn = warp >> 1;            // 2 x 4 warp grid
    int m0 = blockIdx.y * 128, n0 = blockIdx.x * 128;
    int nc = Kdim >> 6;

    float acc[4][4][4];                            // [mt][nt][4]
#pragma unroll
    for (int mt = 0; mt < 4; mt++)
#pragma unroll
        for (int nt = 0; nt < 4; nt++)
#pragma unroll
            for (int i = 0; i < 4; i++) acc[mt][nt][i] = 0.f;

    // fragment address components (tile-local rows)
    int a_r = (lane & 15);                         // + wm*64 + mt*16
    int a_kq_h = (lane >> 4);                      // + 2*ks
    int b_r = (lane & 7) + ((lane & 16) ? 8 : 0);  // + wn*32 + h*16
    int b_kq_h = (lane >> 3) & 1;                  // + 2*ks

    stage_gb(sb, 0, Ahi, Alo, Bhi, Blo, m0, n0, Kdim, 0, tid);
    cp_commit();

    for (int c = 0; c < nc; c++) {
        int buf = c & 1;
        if (c + 1 < nc) {
            stage_gb(sb, 1 - buf, Ahi, Alo, Bhi, Blo, m0, n0, Kdim, c + 1, tid);
            cp_commit();
            cp_wait<1>();
        } else {
            cp_wait<0>();
        }
        __syncthreads();

        uint32_t base = sb + buf * GB_BUF;
#pragma unroll
        for (int ks = 0; ks < 4; ks++) {
            uint32_t ahf[4][4], alf[4][4];
            int akq = 2 * ks + a_kq_h;
#pragma unroll
            for (int mt = 0; mt < 4; mt++) {
                int r = wm * 64 + mt * 16 + a_r;
                uint32_t ad = base + r * 128 + ((akq ^ (r & 7)) << 4);
                ldsm_x4(ahf[mt], ad);
                ldsm_x4(alf[mt], ad + 16384);
            }
            uint32_t bhf[4][2], blf[4][2];
            int bkq = 2 * ks + b_kq_h;
#pragma unroll
            for (int h = 0; h < 2; h++) {
                int r = wn * 32 + h * 16 + b_r;
                uint32_t bd = base + 32768 + r * 128 + ((bkq ^ (r & 7)) << 4);
                uint32_t t[4];
                ldsm_x4(t, bd);
                bhf[2 * h][0] = t[0]; bhf[2 * h][1] = t[1];
                bhf[2 * h + 1][0] = t[2]; bhf[2 * h + 1][1] = t[3];
                ldsm_x4(t, bd + 16384);
                blf[2 * h][0] = t[0]; blf[2 * h][1] = t[1];
                blf[2 * h + 1][0] = t[2]; blf[2 * h + 1][1] = t[3];
            }
#pragma unroll
            for (int mt = 0; mt < 4; mt++)
#pragma unroll
                for (int nt = 0; nt < 4; nt++) {
                    mma_bf16(acc[mt][nt], ahf[mt], bhf[nt]);
                    mma_bf16(acc[mt][nt], ahf[mt], blf[nt]);
                    mma_bf16(acc[mt][nt], alf[mt], bhf[nt]);
                }
        }
        __syncthreads();
    }

    // epilogue
#pragma unroll
    for (int mt = 0; mt < 4; mt++) {
#pragma unroll
        for (int half = 0; half < 2; half++) {
            int m = m0 + wm * 64 + mt * 16 + (lane >> 2) + half * 8;
            float* crow = Cm + (size_t)m * Ndim + n0 + wn * 32;
            const float* rrow =
                RESID ? (Rin + (size_t)m * Ndim + n0 + wn * 32) : nullptr;
#pragma unroll
            for (int nt = 0; nt < 4; nt++) {
                int coff = nt * 8 + 2 * (lane & 3);
                float2 v;
                v.x = acc[mt][nt][half * 2 + 0];
                v.y = acc[mt][nt][half * 2 + 1];
                if (RESID) {
                    float2 rv = *(const float2*)(rrow + coff);
                    v.x += rv.x; v.y += rv.y;
                }
                *(float2*)(crow + coff) = v;
            }
        }
    }
}

// ---------------- silu(gate) * up, elementwise ----------------
__global__ void silu_mul_kernel() {
    int idx = blockIdx.x * blockDim.x + threadIdx.x;
    if (idx >= MTOK * DFF / 4) return;
    float4 g = ((const float4*)g_act)[idx];
    float4 u = ((const float4*)g_up)[idx];
    float4 o;
    o.x = g.x / (1.f + __expf(-g.x)) * u.x;
    o.y = g.y / (1.f + __expf(-g.y)) * u.y;
    o.z = g.z / (1.f + __expf(-g.z)) * u.z;
    o.w = g.w / (1.f + __expf(-g.w)) * u.w;
    ((float4*)g_act)[idx] = o;
}

// ---------------- flash attention (fp32, online softmax, ALiBi) ----------------
#define ATTN_SMEM_FLOATS 13760
#define ATTN_SMEM_BYTES (ATTN_SMEM_FLOATS * 4)

__global__ void __launch_bounds__(128)
attn_kernel(const float* __restrict__ log_slopes) {
    extern __shared__ float sm[];
    float (*Qs)[49] = (float(*)[49])sm;             // 64x49
    float (*Ks)[49] = (float(*)[49])(sm + 3136);    // 64x49
    float (*Vs)[49] = (float(*)[49])(sm + 6272);    // 64x49
    float (*Ps)[65] = (float(*)[65])(sm + 9408);    // 64x65
    float* mrow = sm + 13568;
    float* lrow = sm + 13632;
    float* crow = sm + 13696;

    int qt = blockIdx.x;
    int bh = blockIdx.y;
    int b = bh >> 4, h = bh & 15;
    int tid = threadIdx.x;
    int a = tid >> 3;   // 0..15
    int b8 = tid & 7;   // 0..7
    float slope = expf(log_slopes[h]);
    const float scale = 0.14433756729740643f;  // 1/sqrt(48)
    int q0 = qt * 64;
    const float* qkvb = g_qkv + (long)b * SEQ * (3 * DM);

    for (int i = tid; i < 64 * 12; i += 128) {
        int r = i / 12, c4 = (i % 12) * 4;
        float4 v = *(const float4*)(qkvb + (long)(q0 + r) * (3 * DM) + h * HDIM + c4);
        Qs[r][c4 + 0] = v.x; Qs[r][c4 + 1] = v.y;
        Qs[r][c4 + 2] = v.z; Qs[r][c4 + 3] = v.w;
    }
    if (tid < 64) { mrow[tid] = -1e30f; lrow[tid] = 0.f; }
    float oacc[4][6];
#pragma unroll
    for (int r = 0; r < 4; r++)
#pragma unroll
        for (int c = 0; c < 6; c++) oacc[r][c] = 0.f;
    __syncthreads();

    for (int kt = 0; kt < SEQ; kt += 64) {
        for (int i = tid; i < 64 * 12; i += 128) {
            int r = i / 12, c4 = (i % 12) * 4;
            const float* kp = qkvb + (long)(kt + r) * (3 * DM) + DM + h * HDIM + c4;
            float4 kv = *(const float4*)kp;
            Ks[r][c4 + 0] = kv.x; Ks[r][c4 + 1] = kv.y;
            Ks[r][c4 + 2] = kv.z; Ks[r][c4 + 3] = kv.w;
            float4 vv = *(const float4*)(kp + DM);
            Vs[r][c4 + 0] = vv.x; Vs[r][c4 + 1] = vv.y;
            Vs[r][c4 + 2] = vv.z; Vs[r][c4 + 3] = vv.w;
        }
        __syncthreads();

        float sacc[4][8];
#pragma unroll
        for (int r = 0; r < 4; r++)
#pragma unroll
            for (int c = 0; c < 8; c++) sacc[r][c] = 0.f;
#pragma unroll 8
        for (int k = 0; k < HDIM; k++) {
            float ar[4], br[8];
#pragma unroll
            for (int r = 0; r < 4; r++) ar[r] = Qs[a * 4 + r][k];
#pragma unroll
            for (int c = 0; c < 8; c++) br[c] = Ks[b8 * 8 + c][k];
#pragma unroll
            for (int r = 0; r < 4; r++)
#pragma unroll
                for (int c = 0; c < 8; c++) sacc[r][c] += ar[r] * br[c];
        }
#pragma unroll
        for (int r = 0; r < 4; r++)
#pragma unroll
            for (int c = 0; c < 8; c++) {
                int qi = q0 + a * 4 + r;
                int kj = kt + b8 * 8 + c;
                Ps[a * 4 + r][b8 * 8 + c] =
                    sacc[r][c] * scale - slope * fabsf((float)(qi - kj));
            }
        __syncthreads();

        if (tid < 64) {
            int row = tid;
            float mold = mrow[row];
            float mx = mold;
#pragma unroll 8
            for (int j = 0; j < 64; j++) mx = fmaxf(mx, Ps[row][j]);
            float corr = __expf(mold - mx);
            float sum = 0.f;
#pragma unroll 8
            for (int j = 0; j < 64; j++) {
                float p = __expf(Ps[row][j] - mx);
                Ps[row][j] = p;
                sum += p;
            }
            lrow[row] = lrow[row] * corr + sum;
            mrow[row] = mx;
            crow[row] = corr;
        }
        __syncthreads();

        float cr[4];
#pragma unroll
        for (int r = 0; r < 4; r++) cr[r] = crow[a * 4 + r];
#pragma unroll
        for (int r = 0; r < 4; r++)
#pragma unroll
            for (int c = 0; c < 6; c++) oacc[r][c] *= cr[r];
#pragma unroll 8
        for (int j = 0; j < 64; j++) {
            float pv[4], vv[6];
#pragma unroll
            for (int r = 0; r < 4; r++) pv[r] = Ps[a * 4 + r][j];
#pragma unroll
            for (int c = 0; c < 6; c++) vv[c] = Vs[j][b8 * 6 + c];
#pragma unroll
            for (int r = 0; r < 4; r++)
#pragma unroll
                for (int c = 0; c < 6; c++) oacc[r][c] += pv[r] * vv[c];
        }
        __syncthreads();
    }

#pragma unroll
    for (int r = 0; r < 4; r++) {
        int row = a * 4 + r;
        float inv = 1.f / lrow[row];
#pragma unroll
        for (int c = 0; c < 6; c++) {
            g_o[(long)(b * SEQ + q0 + row) * DM + h * HDIM + b8 * 6 + c] =
                oacc[r][c] * inv;
        }
    }
}

// ---------------- launch ----------------
static inline void launch_split(const float* src, __nv_bfloat16* hi,
                                __nv_bfloat16* lo, long n) {
    int n4 = (int)(n / 4);
    split_kernel<<<(n4 + 255) / 256, 256>>>(src, hi, lo, n4);
}

extern "C" void kernel_launch(void* const* d_in, const int* in_sizes, int n_in,
                              void* d_out, int out_size) {
    (void)in_sizes; (void)n_in; (void)out_size;
    const float* cls_tokens = (const float*)d_in[0];
    const float* cls_token  = (const float*)d_in[1];
    const float* log_slopes = (const float*)d_in[2];
    const float* Wqkv = (const float*)d_in[3];
    const float* Wo   = (const float*)d_in[4];
    const float* Wg   = (const float*)d_in[5];
    const float* Wu   = (const float*)d_in[6];
    const float* Wd   = (const float*)d_in[7];
    const float* ln1w = (const float*)d_in[8];
    const float* ln1b = (const float*)d_in[9];
    const float* ln2w = (const float*)d_in[10];
    const float* ln2b = (const float*)d_in[11];
    const float* finw = (const float*)d_in[12];
    const float* finb = (const float*)d_in[13];
    float* out = (float*)d_out;

    float *px, *ph, *pqkv, *po, *pact, *pup;
    __nv_bfloat16 *pwhi, *pwlo, *pahi, *palo;
    cudaGetSymbolAddress((void**)&px, g_x);
    cudaGetSymbolAddress((void**)&ph, g_h);
    cudaGetSymbolAddress((void**)&pqkv, g_qkv);
    cudaGetSymbolAddress((void**)&po, g_o);
    cudaGetSymbolAddress((void**)&pact, g_act);
    cudaGetSymbolAddress((void**)&pup, g_up);
    cudaGetSymbolAddress((void**)&pwhi, g_whi);
    cudaGetSymbolAddress((void**)&pwlo, g_wlo);
    cudaGetSymbolAddress((void**)&pahi, g_ahi);
    cudaGetSymbolAddress((void**)&palo, g_alo);

    cudaFuncSetAttribute(attn_kernel,
                         cudaFuncAttributeMaxDynamicSharedMemorySize,
                         ATTN_SMEM_BYTES);
    cudaFuncSetAttribute(gemm_bf16<false>,
                         cudaFuncAttributeMaxDynamicSharedMemorySize, GB_SMEM);
    cudaFuncSetAttribute(gemm_bf16<true>,
                         cudaFuncAttributeMaxDynamicSharedMemorySize, GB_SMEM);

    // pre-split all weights (hi/lo bf16)
    for (int l = 0; l < NL; l++) {
        long base = (long)l * WSZ_LAYER;
        launch_split(Wqkv + (long)l * WSZ_QKV, pwhi + base + WOFF_QKV,
                     pwlo + base + WOFF_QKV, WSZ_QKV);
        launch_split(Wo + (long)l * WSZ_O, pwhi + base + WOFF_O,
                     pwlo + base + WOFF_O, WSZ_O);
        launch_split(Wg + (long)l * WSZ_G, pwhi + base + WOFF_G,
                     pwlo + base + WOFF_G, WSZ_G);
        launch_split(Wu + (long)l * WSZ_U, pwhi + base + WOFF_U,
                     pwlo + base + WOFF_U, WSZ_U);
        launch_split(Wd + (long)l * WSZ_D, pwhi + base + WOFF_D,
                     pwlo + base + WOFF_D, WSZ_D);
    }

    embed_kernel<<<(MTOK * DM + 255) / 256, 256>>>(cls_tokens, cls_token);

    for (int l = 0; l < NL; l++) {
        long wb = (long)l * WSZ_LAYER;
        ln_kernel<<<MTOK, 256>>>(px, DM, ph, ln1w + l * DM, ln1b + l * DM);
        launch_split(ph, pahi, palo, (long)MTOK * DM);
        gemm_bf16<false><<<dim3(3 * DM / 128, MTOK / 128), 256, GB_SMEM>>>(
            pahi, palo, pwhi + wb + WOFF_QKV, pwlo + wb + WOFF_QKV,
            nullptr, pqkv, 3 * DM, DM);
        attn_kernel<<<dim3(SEQ / 64, NB * NH), 128, ATTN_SMEM_BYTES>>>(log_slopes);
        launch_split(po, pahi, palo, (long)MTOK * DM);
        gemm_bf16<true><<<dim3(DM / 128, MTOK / 128), 256, GB_SMEM>>>(
            pahi, palo, pwhi + wb + WOFF_O, pwlo + wb + WOFF_O,
            px, px, DM, DM);
        ln_kernel<<<MTOK, 256>>>(px, DM, ph, ln2w + l * DM, ln2b + l * DM);
        launch_split(ph, pahi, palo, (long)MTOK * DM);
        gemm_bf16<false><<<dim3(DFF / 128, MTOK / 128), 256, GB_SMEM>>>(
            pahi, palo, pwhi + wb + WOFF_G, pwlo + wb + WOFF_G,
            nullptr, pact, DFF, DM);
        gemm_bf16<false><<<dim3(DFF / 128, MTOK / 128), 256, GB_SMEM>>>(
            pahi, palo, pwhi + wb + WOFF_U, pwlo + wb + WOFF_U,
            nullptr, pup, DFF, DM);
        silu_mul_kernel<<<(MTOK * DFF / 4 + 255) / 256, 256>>>();
        launch_split(pact, pahi, palo, (long)MTOK * DFF);
        gemm_bf16<true><<<dim3(DM / 128, MTOK / 128), 256, GB_SMEM>>>(
            pahi, palo, pwhi + wb + WOFF_D, pwlo + wb + WOFF_D,
            px, px, DM, DFF);
    }

    ln_kernel<<<NB, 256>>>(px, SEQ * DM, out, finw, finb);
}

// round 16
// speedup vs baseline: 2.8816x; 1.3395x over previous
#include <cuda_runtime.h>
#include <cuda_bf16.h>
#include <math.h>
#include <stdint.h>

#define NL 6
#define NH 16
#define DM 768
#define DFF 3072
#define NB 4
#define NTOKS 1023
#define SEQ 1024
#define HDIM 48
#define MTOK (NB * SEQ)      // 4096 tokens
#define LN_EPS 1e-5f

// weight split layout (elements per layer)
#define WSZ_QKV (3 * DM * DM)
#define WSZ_O   (DM * DM)
#define WSZ_G   (DFF * DM)
#define WSZ_U   (DFF * DM)
#define WSZ_D   (DM * DFF)
#define WSZ_LAYER (WSZ_QKV + WSZ_O + WSZ_G + WSZ_U + WSZ_D)
#define WOFF_QKV 0
#define WOFF_O   (WSZ_QKV)
#define WOFF_G   (WSZ_QKV + WSZ_O)
#define WOFF_U   (WSZ_QKV + WSZ_O + WSZ_G)
#define WOFF_D   (WSZ_QKV + WSZ_O + WSZ_G + WSZ_U)
#define WSZ_ALL  (WSZ_LAYER * NL)

// ---------------- scratch (device globals; no allocation APIs) ----------------
__device__ float g_x[MTOK * DM];            // residual stream
__device__ float g_act[MTOK * DFF];         // gate gemm out
__device__ float g_up[MTOK * DFF];          // up gemm out
__device__ __nv_bfloat16 g_whi[WSZ_ALL];    // weight hi parts
__device__ __nv_bfloat16 g_wlo[WSZ_ALL];    // weight lo parts
__device__ __nv_bfloat16 g_ahi[MTOK * DFF]; // activation hi (GEMM A operand)
__device__ __nv_bfloat16 g_alo[MTOK * DFF]; // activation lo
__device__ __nv_bfloat16 g_qkvh[MTOK * 3 * DM]; // qkv hi
__device__ __nv_bfloat16 g_qkvl[MTOK * 3 * DM]; // qkv lo

// ---------------- ptx helpers (sm_80-era; tcgen05 unavailable on sm_103) -----
__device__ __forceinline__ uint32_t smem_u32(const void* p) {
    uint32_t a;
    asm("{ .reg .u64 t; cvta.to.shared.u64 t, %1; cvt.u32.u64 %0, t; }"
        : "=r"(a) : "l"(p));
    return a;
}
__device__ __forceinline__ void ldsm_x4(uint32_t* r, uint32_t addr) {
    asm volatile("ldmatrix.sync.aligned.m8n8.x4.shared.b16 {%0,%1,%2,%3}, [%4];"
                 : "=r"(r[0]), "=r"(r[1]), "=r"(r[2]), "=r"(r[3]) : "r"(addr));
}
__device__ __forceinline__ void ldsm_x4_t(uint32_t* r, uint32_t addr) {
    asm volatile("ldmatrix.sync.aligned.m8n8.x4.trans.shared.b16 {%0,%1,%2,%3}, [%4];"
                 : "=r"(r[0]), "=r"(r[1]), "=r"(r[2]), "=r"(r[3]) : "r"(addr));
}
__device__ __forceinline__ void mma_bf16(float* d, const uint32_t* a,
                                         const uint32_t* b) {
    asm volatile(
        "mma.sync.aligned.m16n8k16.row.col.f32.bf16.bf16.f32 "
        "{%0,%1,%2,%3}, {%4,%5,%6,%7}, {%8,%9}, {%0,%1,%2,%3};"
        : "+f"(d[0]), "+f"(d[1]), "+f"(d[2]), "+f"(d[3])
        : "r"(a[0]), "r"(a[1]), "r"(a[2]), "r"(a[3]), "r"(b[0]), "r"(b[1]));
}
__device__ __forceinline__ void cp16(uint32_t smem, const void* g) {
    asm volatile("cp.async.ca.shared.global [%0], [%1], 16;"
                 :: "r"(smem), "l"(g) : "memory");
}
__device__ __forceinline__ void cp_commit() {
    asm volatile("cp.async.commit_group;" ::: "memory");
}
template <int N>
__device__ __forceinline__ void cp_wait() {
    asm volatile("cp.async.wait_group %0;" :: "n"(N) : "memory");
}
__device__ __forceinline__ uint32_t bf2_u32(__nv_bfloat162 v) {
    return *reinterpret_cast<uint32_t*>(&v);
}

// ---------------- bf16 hi/lo split (weights only now) ----------------
__global__ void split_kernel(const float* __restrict__ src,
                             __nv_bfloat16* __restrict__ hi,
                             __nv_bfloat16* __restrict__ lo, int n4) {
    int i = blockIdx.x * blockDim.x + threadIdx.x;
    if (i >= n4) return;
    float4 v = ((const float4*)src)[i];
    __nv_bfloat162 h01 = __floats2bfloat162_rn(v.x, v.y);
    __nv_bfloat162 h23 = __floats2bfloat162_rn(v.z, v.w);
    __nv_bfloat162 l01 = __floats2bfloat162_rn(v.x - __low2float(h01),
                                               v.y - __high2float(h01));
    __nv_bfloat162 l23 = __floats2bfloat162_rn(v.z - __low2float(h23),
                                               v.w - __high2float(h23));
    ((__nv_bfloat162*)hi)[2 * i] = h01;
    ((__nv_bfloat162*)hi)[2 * i + 1] = h23;
    ((__nv_bfloat162*)lo)[2 * i] = l01;
    ((__nv_bfloat162*)lo)[2 * i + 1] = l23;
}

// ---------------- embed ----------------
__global__ void embed_kernel(const float* __restrict__ cls_tokens,
                             const float* __restrict__ cls_token) {
    int idx = blockIdx.x * blockDim.x + threadIdx.x;
    if (idx >= MTOK * DM) return;
    int d = idx % DM;
    int tok = idx / DM;
    int b = tok / SEQ, s = tok % SEQ;
    g_x[idx] = (s == 0) ? cls_token[d]
                        : cls_tokens[(b * NTOKS + (s - 1)) * DM + d];
}

// ---------------- layernorm -> split bf16 output ----------------
__global__ void ln_split_kernel(const float* __restrict__ src,
                                const float* __restrict__ w,
                                const float* __restrict__ bias,
                                __nv_bfloat16* __restrict__ hi,
                                __nv_bfloat16* __restrict__ lo) {
    int row = blockIdx.x;
    const float* xp = src + (long)row * DM;
    int tid = threadIdx.x;  // 256
    float v0 = xp[tid], v1 = xp[tid + 256], v2 = xp[tid + 512];
    float s1 = v0 + v1 + v2;
    float s2 = v0 * v0 + v1 * v1 + v2 * v2;
#pragma unroll
    for (int off = 16; off > 0; off >>= 1) {
        s1 += __shfl_xor_sync(0xffffffff, s1, off);
        s2 += __shfl_xor_sync(0xffffffff, s2, off);
    }
    __shared__ float sm1[8], sm2[8];
    int wid = tid >> 5, lid = tid & 31;
    if (lid == 0) { sm1[wid] = s1; sm2[wid] = s2; }
    __syncthreads();
    if (wid == 0) {
        float t1 = (lid < 8) ? sm1[lid] : 0.f;
        float t2 = (lid < 8) ? sm2[lid] : 0.f;
#pragma unroll
        for (int off = 4; off > 0; off >>= 1) {
            t1 += __shfl_xor_sync(0xffffffff, t1, off);
            t2 += __shfl_xor_sync(0xffffffff, t2, off);
        }
        if (lid == 0) { sm1[0] = t1; sm2[0] = t2; }
    }
    __syncthreads();
    float mean = sm1[0] * (1.f / DM);
    float var = sm2[0] * (1.f / DM) - mean * mean;
    float rstd = rsqrtf(var + LN_EPS);
    long base = (long)row * DM;
#pragma unroll
    for (int j = 0; j < 3; j++) {
        int col = tid + j * 256;
        float v = (j == 0 ? v0 : (j == 1 ? v1 : v2));
        float y = (v - mean) * rstd * w[col] + bias[col];
        __nv_bfloat16 hv = __float2bfloat16(y);
        hi[base + col] = hv;
        lo[base + col] = __float2bfloat16(y - __bfloat162float(hv));
    }
}

// ---------------- final layernorm (fp32 out) ----------------
__global__ void ln_final_kernel(const float* __restrict__ src, int src_row_stride,
                                float* __restrict__ dst,
                                const float* __restrict__ w,
                                const float* __restrict__ bias) {
    int row = blockIdx.x;
    const float* xp = src + (long)row * src_row_stride;
    float* yp = dst + (long)row * DM;
    int tid = threadIdx.x;  // 256
    float v0 = xp[tid], v1 = xp[tid + 256], v2 = xp[tid + 512];
    float s1 = v0 + v1 + v2;
    float s2 = v0 * v0 + v1 * v1 + v2 * v2;
#pragma unroll
    for (int off = 16; off > 0; off >>= 1) {
        s1 += __shfl_xor_sync(0xffffffff, s1, off);
        s2 += __shfl_xor_sync(0xffffffff, s2, off);
    }
    __shared__ float sm1[8], sm2[8];
    int wid = tid >> 5, lid = tid & 31;
    if (lid == 0) { sm1[wid] = s1; sm2[wid] = s2; }
    __syncthreads();
    if (wid == 0) {
        float t1 = (lid < 8) ? sm1[lid] : 0.f;
        float t2 = (lid < 8) ? sm2[lid] : 0.f;
#pragma unroll
        for (int off = 4; off > 0; off >>= 1) {
            t1 += __shfl_xor_sync(0xffffffff, t1, off);
            t2 += __shfl_xor_sync(0xffffffff, t2, off);
        }
        if (lid == 0) { sm1[0] = t1; sm2[0] = t2; }
    }
    __syncthreads();
    float mean = sm1[0] * (1.f / DM);
    float var = sm2[0] * (1.f / DM) - mean * mean;
    float rstd = rsqrtf(var + LN_EPS);
    yp[tid]       = (v0 - mean) * rstd * w[tid]       + bias[tid];
    yp[tid + 256] = (v1 - mean) * rstd * w[tid + 256] + bias[tid + 256];
    yp[tid + 512] = (v2 - mean) * rstd * w[tid + 512] + bias[tid + 512];
}

// ---------------- bf16 tensor-core GEMM (NT): C = A @ B^T ---------------
// OMODE: 0 = fp32 out, 1 = fp32 out + residual, 2 = split bf16 out.
// Tile M128 x N128, 256 threads = 8 warps (2x4); warp tile 64x32.
// K chunks of 64, double-buffered cp.async. 3-term hi/lo compensation.
#define GB_BUF 65536
#define GB_SMEM (2 * GB_BUF)

__device__ __forceinline__ void stage_gb(
    uint32_t sb, int buf,
    const __nv_bfloat16* __restrict__ Ahi, const __nv_bfloat16* __restrict__ Alo,
    const __nv_bfloat16* __restrict__ Bhi, const __nv_bfloat16* __restrict__ Blo,
    int m0, int n0, int Kdim, int c, int tid) {
    uint32_t base = sb + buf * GB_BUF;
    size_t ka = (size_t)m0 * Kdim + c * 64;
    size_t kb = (size_t)n0 * Kdim + c * 64;
#pragma unroll
    for (int i = 0; i < 4; i++) {
        int u = i * 256 + tid;               // 0..1023
        int r = u >> 3, kq = u & 7;
        uint32_t d = base + r * 128 + ((kq ^ (r & 7)) << 4);
        size_t sa = ka + (size_t)r * Kdim + kq * 8;
        size_t sbn = kb + (size_t)r * Kdim + kq * 8;
        cp16(d,         Ahi + sa);
        cp16(d + 16384, Alo + sa);
        cp16(d + 32768, Bhi + sbn);
        cp16(d + 49152, Blo + sbn);
    }
}

template <int OMODE>
__global__ void __launch_bounds__(256, 1)
gemm_bf16(const __nv_bfloat16* __restrict__ Ahi, const __nv_bfloat16* __restrict__ Alo,
          const __nv_bfloat16* __restrict__ Bhi, const __nv_bfloat16* __restrict__ Blo,
          const float* __restrict__ Rin, float* __restrict__ Cm,
          __nv_bfloat16* __restrict__ Chi, __nv_bfloat16* __restrict__ Clo,
          int Ndim, int Kdim) {
    extern __shared__ char smem[];
    uint32_t sb = smem_u32(smem);
    int tid = threadIdx.x;
    int lane = tid & 31, warp = tid >> 5;
    int wm = warp & 1, wn = warp >> 1;            // 2 x 4 warp grid
    int m0 = blockIdx.y * 128, n0 = blockIdx.x * 128;
    int nc = Kdim >> 6;

    float acc[4][4][4];
#pragma unroll
    for (int mt = 0; mt < 4; mt++)
#pragma unroll
        for (int nt = 0; nt < 4; nt++)
#pragma unroll
            for (int i = 0; i < 4; i++) acc[mt][nt][i] = 0.f;

    int a_r = (lane & 15);
    int a_kq_h = (lane >> 4);
    int b_r = (lane & 7) + ((lane & 16) ? 8 : 0);
    int b_kq_h = (lane >> 3) & 1;

    stage_gb(sb, 0, Ahi, Alo, Bhi, Blo, m0, n0, Kdim, 0, tid);
    cp_commit();

    for (int c = 0; c < nc; c++) {
        int buf = c & 1;
        if (c + 1 < nc) {
            stage_gb(sb, 1 - buf, Ahi, Alo, Bhi, Blo, m0, n0, Kdim, c + 1, tid);
            cp_commit();
            cp_wait<1>();
        } else {
            cp_wait<0>();
        }
        __syncthreads();

        uint32_t base = sb + buf * GB_BUF;
#pragma unroll
        for (int ks = 0; ks < 4; ks++) {
            uint32_t ahf[4][4], alf[4][4];
            int akq = 2 * ks + a_kq_h;
#pragma unroll
            for (int mt = 0; mt < 4; mt++) {
                int r = wm * 64 + mt * 16 + a_r;
                uint32_t ad = base + r * 128 + ((akq ^ (r & 7)) << 4);
                ldsm_x4(ahf[mt], ad);
                ldsm_x4(alf[mt], ad + 16384);
            }
            uint32_t bhf[4][2], blf[4][2];
            int bkq = 2 * ks + b_kq_h;
#pragma unroll
            for (int h = 0; h < 2; h++) {
                int r = wn * 32 + h * 16 + b_r;
                uint32_t bd = base + 32768 + r * 128 + ((bkq ^ (r & 7)) << 4);
                uint32_t t[4];
                ldsm_x4(t, bd);
                bhf[2 * h][0] = t[0]; bhf[2 * h][1] = t[1];
                bhf[2 * h + 1][0] = t[2]; bhf[2 * h + 1][1] = t[3];
                ldsm_x4(t, bd + 16384);
                blf[2 * h][0] = t[0]; blf[2 * h][1] = t[1];
                blf[2 * h + 1][0] = t[2]; blf[2 * h + 1][1] = t[3];
            }
#pragma unroll
            for (int mt = 0; mt < 4; mt++)
#pragma unroll
                for (int nt = 0; nt < 4; nt++) {
                    mma_bf16(acc[mt][nt], ahf[mt], bhf[nt]);
                    mma_bf16(acc[mt][nt], ahf[mt], blf[nt]);
                    mma_bf16(acc[mt][nt], alf[mt], bhf[nt]);
                }
        }
        __syncthreads();
    }

    // epilogue
#pragma unroll
    for (int mt = 0; mt < 4; mt++) {
#pragma unroll
        for (int half = 0; half < 2; half++) {
            int m = m0 + wm * 64 + mt * 16 + (lane >> 2) + half * 8;
            size_t rowoff = (size_t)m * Ndim + n0 + wn * 32;
#pragma unroll
            for (int nt = 0; nt < 4; nt++) {
                int coff = nt * 8 + 2 * (lane & 3);
                float vx = acc[mt][nt][half * 2 + 0];
                float vy = acc[mt][nt][half * 2 + 1];
                if (OMODE == 2) {
                    __nv_bfloat162 hh = __floats2bfloat162_rn(vx, vy);
                    __nv_bfloat162 ll = __floats2bfloat162_rn(
                        vx - __low2float(hh), vy - __high2float(hh));
                    *(__nv_bfloat162*)(Chi + rowoff + coff) = hh;
                    *(__nv_bfloat162*)(Clo + rowoff + coff) = ll;
                } else {
                    float2 v; v.x = vx; v.y = vy;
                    if (OMODE == 1) {
                        float2 rv = *(const float2*)(Rin + rowoff + coff);
                        v.x += rv.x; v.y += rv.y;
                    }
                    *(float2*)(Cm + rowoff + coff) = v;
                }
            }
        }
    }
}

// ---------------- silu(gate) * up -> split bf16 ----------------
__global__ void silu_split_kernel() {
    int idx = blockIdx.x * blockDim.x + threadIdx.x;
    if (idx >= MTOK * DFF / 4) return;
    float4 g = ((const float4*)g_act)[idx];
    float4 u = ((const float4*)g_up)[idx];
    float a0 = g.x / (1.f + __expf(-g.x)) * u.x;
    float a1 = g.y / (1.f + __expf(-g.y)) * u.y;
    float a2 = g.z / (1.f + __expf(-g.z)) * u.z;
    float a3 = g.w / (1.f + __expf(-g.w)) * u.w;
    __nv_bfloat162 h01 = __floats2bfloat162_rn(a0, a1);
    __nv_bfloat162 h23 = __floats2bfloat162_rn(a2, a3);
    __nv_bfloat162 l01 = __floats2bfloat162_rn(a0 - __low2float(h01),
                                               a1 - __high2float(h01));
    __nv_bfloat162 l23 = __floats2bfloat162_rn(a2 - __low2float(h23),
                                               a3 - __high2float(h23));
    ((__nv_bfloat162*)g_ahi)[2 * idx] = h01;
    ((__nv_bfloat162*)g_ahi)[2 * idx + 1] = h23;
    ((__nv_bfloat162*)g_alo)[2 * idx] = l01;
    ((__nv_bfloat162*)g_alo)[2 * idx + 1] = l23;
}

// ---------------- tensor-core flash attention (bf16 3-term, ALiBi) ---------
// grid (SEQ/64, B*H), 128 threads = 4 warps; warp handles 16 q rows.
// smem: Qh 8K | Ql 8K | 2 x { Kh 8K | Kl 8K | Vh 8K | Vl 8K }
#define AT_SMEM 81920

__device__ __forceinline__ void stage_att_kv(
    uint32_t sb, int buf, const __nv_bfloat16* __restrict__ qh,
    const __nv_bfloat16* __restrict__ ql, int brow0, int h, int tid) {
    uint32_t base = sb + 16384 + buf * 32768;
#pragma unroll
    for (int i = 0; i < 3; i++) {
        int u = i * 128 + tid;               // 0..383
        int r = u / 6, c = u - r * 6;
        uint32_t d = base + r * 128 + ((c ^ (r & 7)) << 4);
        size_t src = (size_t)(brow0 + r) * (3 * DM) + DM + h * HDIM + c * 8;
        cp16(d,         qh + src);           // K hi
        cp16(d + 8192,  ql + src);           // K lo
        cp16(d + 16384, qh + src + DM);      // V hi
        cp16(d + 24576, ql + src + DM);      // V lo
    }
}

__global__ void __launch_bounds__(128)
attn_tc(const float* __restrict__ log_slopes,
        const __nv_bfloat16* __restrict__ qh, const __nv_bfloat16* __restrict__ ql,
        __nv_bfloat16* __restrict__ ohi, __nv_bfloat16* __restrict__ olo) {
    extern __shared__ char smem[];
    uint32_t sb = smem_u32(smem);
    int qt = blockIdx.x, bh = blockIdx.y;
    int b = bh >> 4, h = bh & 15;
    int tid = threadIdx.x, lane = tid & 31, w = tid >> 5;
    int q0 = qt * 64;
    float slope = expf(log_slopes[h]);
    const float scale = 0.14433756729740643f;  // 1/sqrt(48)

    // stage Q tile + first K/V tile
#pragma unroll
    for (int i = 0; i < 3; i++) {
        int u = i * 128 + tid;
        int r = u / 6, c = u - r * 6;
        uint32_t d = sb + r * 128 + ((c ^ (r & 7)) << 4);
        size_t src = (size_t)(b * SEQ + q0 + r) * (3 * DM) + h * HDIM + c * 8;
        cp16(d,        qh + src);
        cp16(d + 8192, ql + src);
    }
    stage_att_kv(sb, 0, qh, ql, b * SEQ, h, tid);
    cp_commit();

    uint32_t qah[3][4], qal[3][4];       // Q fragments (iter-invariant)
    float oacc[6][4];
#pragma unroll
    for (int nt = 0; nt < 6; nt++)
#pragma unroll
        for (int i = 0; i < 4; i++) oacc[nt][i] = 0.f;
    float m_a = -1e30f, m_b = -1e30f, l_a = 0.f, l_b = 0.f;

    int qa = q0 + w * 16 + (lane >> 2);  // row a global q index
    int b_r = (lane & 7) + ((lane & 16) ? 8 : 0);
    int b_kq_h = (lane >> 3) & 1;

    for (int it = 0; it < SEQ / 64; it++) {
        if (it + 1 < SEQ / 64) {
            stage_att_kv(sb, (it + 1) & 1, qh, ql, b * SEQ + (it + 1) * 64, h, tid);
            cp_commit();
            cp_wait<1>();
        } else {
            cp_wait<0>();
        }
        __syncthreads();

        if (it == 0) {
#pragma unroll
            for (int ks = 0; ks < 3; ks++) {
                int akq = 2 * ks + (lane >> 4);
                int r = w * 16 + (lane & 15);
                uint32_t ad = sb + r * 128 + ((akq ^ (r & 7)) << 4);
                ldsm_x4(qah[ks], ad);
                ldsm_x4(qal[ks], ad + 8192);
            }
        }

        uint32_t kbase = sb + 16384 + (it & 1) * 32768;
        // ---- scores: 16(q) x 64(k) per warp ----
        float sacc[8][4];
#pragma unroll
        for (int nt = 0; nt < 8; nt++)
#pragma unroll
            for (int i = 0; i < 4; i++) sacc[nt][i] = 0.f;
#pragma unroll
        for (int ks = 0; ks < 3; ks++) {
            int bkq = 2 * ks + b_kq_h;
            uint32_t khf[4][4], klf[4][4];
#pragma unroll
            for (int h4 = 0; h4 < 4; h4++) {
                int r = h4 * 16 + b_r;
                uint32_t ad = kbase + r * 128 + ((bkq ^ (r & 7)) << 4);
                ldsm_x4(khf[h4], ad);
                ldsm_x4(klf[h4], ad + 8192);
            }
#pragma unroll
            for (int h4 = 0; h4 < 4; h4++) {
                mma_bf16(sacc[2 * h4],     qah[ks], khf[h4] + 0);
                mma_bf16(sacc[2 * h4],     qah[ks], klf[h4] + 0);
                mma_bf16(sacc[2 * h4],     qal[ks], khf[h4] + 0);
                mma_bf16(sacc[2 * h4 + 1], qah[ks], khf[h4] + 2);
                mma_bf16(sacc[2 * h4 + 1], qah[ks], klf[h4] + 2);
                mma_bf16(sacc[2 * h4 + 1], qal[ks], khf[h4] + 2);
            }
        }
        // scale + ALiBi bias
#pragma unroll
        for (int nt = 0; nt < 8; nt++) {
            int kj = it * 64 + nt * 8 + 2 * (lane & 3);
            sacc[nt][0] = sacc[nt][0] * scale - slope * fabsf((float)(qa - kj));
            sacc[nt][1] = sacc[nt][1] * scale - slope * fabsf((float)(qa - kj - 1));
            sacc[nt][2] = sacc[nt][2] * scale - slope * fabsf((float)(qa + 8 - kj));
            sacc[nt][3] = sacc[nt][3] * scale - slope * fabsf((float)(qa + 8 - kj - 1));
        }
        // ---- online softmax in registers (quad shuffles) ----
        float mxa = m_a, mxb = m_b;
#pragma unroll
        for (int nt = 0; nt < 8; nt++) {
            mxa = fmaxf(mxa, fmaxf(sacc[nt][0], sacc[nt][1]));
            mxb = fmaxf(mxb, fmaxf(sacc[nt][2], sacc[nt][3]));
        }
        mxa = fmaxf(mxa, __shfl_xor_sync(0xffffffff, mxa, 1));
        mxa = fmaxf(mxa, __shfl_xor_sync(0xffffffff, mxa, 2));
        mxb = fmaxf(mxb, __shfl_xor_sync(0xffffffff, mxb, 1));
        mxb = fmaxf(mxb, __shfl_xor_sync(0xffffffff, mxb, 2));
        float ca = __expf(m_a - mxa), cb = __expf(m_b - mxb);
        float sa = 0.f, sbv = 0.f;
#pragma unroll
        for (int nt = 0; nt < 8; nt++) {
            float p0 = __expf(sacc[nt][0] - mxa);
            float p1 = __expf(sacc[nt][1] - mxa);
            float p2 = __expf(sacc[nt][2] - mxb);
            float p3 = __expf(sacc[nt][3] - mxb);
            sacc[nt][0] = p0; sacc[nt][1] = p1; sacc[nt][2] = p2; sacc[nt][3] = p3;
            sa += p0 + p1; sbv += p2 + p3;
        }
        sa  += __shfl_xor_sync(0xffffffff, sa, 1);
        sa  += __shfl_xor_sync(0xffffffff, sa, 2);
        sbv += __shfl_xor_sync(0xffffffff, sbv, 1);
        sbv += __shfl_xor_sync(0xffffffff, sbv, 2);
        l_a = l_a * ca + sa;  m_a = mxa;
        l_b = l_b * cb + sbv; m_b = mxb;
        // rescale output accumulators
#pragma unroll
        for (int nt = 0; nt < 6; nt++) {
            oacc[nt][0] *= ca; oacc[nt][1] *= ca;
            oacc[nt][2] *= cb; oacc[nt][3] *= cb;
        }
        // ---- PV: P(16x64) @ V(64x48) ----
        uint32_t vbase = kbase + 16384;
        int rk_l = (lane & 15);
#pragma unroll
        for (int kg = 0; kg < 4; kg++) {
            // P fragments from score accs (exact layout match, no shuffles)
            uint32_t phi[4], plo[4];
#pragma unroll
            for (int half = 0; half < 2; half++) {
                const float* p = sacc[2 * kg + half];
                __nv_bfloat162 h01 = __floats2bfloat162_rn(p[0], p[1]);
                __nv_bfloat162 h23 = __floats2bfloat162_rn(p[2], p[3]);
                __nv_bfloat162 l01 = __floats2bfloat162_rn(
                    p[0] - __low2float(h01), p[1] - __high2float(h01));
                __nv_bfloat162 l23 = __floats2bfloat162_rn(
                    p[2] - __low2float(h23), p[3] - __high2float(h23));
                phi[2 * half + 0] = bf2_u32(h01);
                phi[2 * half + 1] = bf2_u32(h23);
                plo[2 * half + 0] = bf2_u32(l01);
                plo[2 * half + 1] = bf2_u32(l23);
            }
            int rk = kg * 16 + rk_l;
            uint32_t vhf[3][4], vlf[3][4];
#pragma unroll
            for (int g3 = 0; g3 < 3; g3++) {
                int cg = 2 * g3 + (lane >> 4);
                uint32_t ad = vbase + rk * 128 + ((cg ^ (rk & 7)) << 4);
                ldsm_x4_t(vhf[g3], ad);
                ldsm_x4_t(vlf[g3], ad + 8192);
            }
#pragma unroll
            for (int g3 = 0; g3 < 3; g3++)
#pragma unroll
                for (int hf = 0; hf < 2; hf++) {
                    int nt = 2 * g3 + hf;
                    mma_bf16(oacc[nt], phi, vhf[g3] + 2 * hf);
                    mma_bf16(oacc[nt], phi, vlf[g3] + 2 * hf);
                    mma_bf16(oacc[nt], plo, vhf[g3] + 2 * hf);
                }
        }
        __syncthreads();
    }

    // epilogue: normalize and write split bf16 output
    float inva = 1.f / l_a, invb = 1.f / l_b;
    size_t tok_a = (size_t)(b * SEQ + qa) * DM + h * HDIM;
    size_t tok_b = tok_a + (size_t)8 * DM;
#pragma unroll
    for (int nt = 0; nt < 6; nt++) {
        int coff = nt * 8 + 2 * (lane & 3);
        float va0 = oacc[nt][0] * inva, va1 = oacc[nt][1] * inva;
        float vb0 = oacc[nt][2] * invb, vb1 = oacc[nt][3] * invb;
        __nv_bfloat162 ha = __floats2bfloat162_rn(va0, va1);
        __nv_bfloat162 la = __floats2bfloat162_rn(va0 - __low2float(ha),
                                                  va1 - __high2float(ha));
        __nv_bfloat162 hb = __floats2bfloat162_rn(vb0, vb1);
        __nv_bfloat162 lb2 = __floats2bfloat162_rn(vb0 - __low2float(hb),
                                                   vb1 - __high2float(hb));
        *(__nv_bfloat162*)(ohi + tok_a + coff) = ha;
        *(__nv_bfloat162*)(olo + tok_a + coff) = la;
        *(__nv_bfloat162*)(ohi + tok_b + coff) = hb;
        *(__nv_bfloat162*)(olo + tok_b + coff) = lb2;
    }
}

// ---------------- launch ----------------
static inline void launch_split(const float* src, __nv_bfloat16* hi,
                                __nv_bfloat16* lo, long n) {
    int n4 = (int)(n / 4);
    split_kernel<<<(n4 + 255) / 256, 256>>>(src, hi, lo, n4);
}

extern "C" void kernel_launch(void* const* d_in, const int* in_sizes, int n_in,
                              void* d_out, int out_size) {
    (void)in_sizes; (void)n_in; (void)out_size;
    const float* cls_tokens = (const float*)d_in[0];
    const float* cls_token  = (const float*)d_in[1];
    const float* log_slopes = (const float*)d_in[2];
    const float* Wqkv = (const float*)d_in[3];
    const float* Wo   = (const float*)d_in[4];
    const float* Wg   = (const float*)d_in[5];
    const float* Wu   = (const float*)d_in[6];
    const float* Wd   = (const float*)d_in[7];
    const float* ln1w = (const float*)d_in[8];
    const float* ln1b = (const float*)d_in[9];
    const float* ln2w = (const float*)d_in[10];
    const float* ln2b = (const float*)d_in[11];
    const float* finw = (const float*)d_in[12];
    const float* finb = (const float*)d_in[13];
    float* out = (float*)d_out;

    float *px, *pact, *pup;
    __nv_bfloat16 *pwhi, *pwlo, *pahi, *palo, *pqh, *pql;
    cudaGetSymbolAddress((void**)&px, g_x);
    cudaGetSymbolAddress((void**)&pact, g_act);
    cudaGetSymbolAddress((void**)&pup, g_up);
    cudaGetSymbolAddress((void**)&pwhi, g_whi);
    cudaGetSymbolAddress((void**)&pwlo, g_wlo);
    cudaGetSymbolAddress((void**)&pahi, g_ahi);
    cudaGetSymbolAddress((void**)&palo, g_alo);
    cudaGetSymbolAddress((void**)&pqh, g_qkvh);
    cudaGetSymbolAddress((void**)&pql, g_qkvl);

    cudaFuncSetAttribute(attn_tc,
                         cudaFuncAttributeMaxDynamicSharedMemorySize, AT_SMEM);
    cudaFuncSetAttribute(gemm_bf16<0>,
                         cudaFuncAttributeMaxDynamicSharedMemorySize, GB_SMEM);
    cudaFuncSetAttribute(gemm_bf16<1>,
                         cudaFuncAttributeMaxDynamicSharedMemorySize, GB_SMEM);
    cudaFuncSetAttribute(gemm_bf16<2>,
                         cudaFuncAttributeMaxDynamicSharedMemorySize, GB_SMEM);

    // pre-split all weights (hi/lo bf16)
    for (int l = 0; l < NL; l++) {
        long base = (long)l * WSZ_LAYER;
        launch_split(Wqkv + (long)l * WSZ_QKV, pwhi + base + WOFF_QKV,
                     pwlo + base + WOFF_QKV, WSZ_QKV);
        launch_split(Wo + (long)l * WSZ_O, pwhi + base + WOFF_O,
                     pwlo + base + WOFF_O, WSZ_O);
        launch_split(Wg + (long)l * WSZ_G, pwhi + base + WOFF_G,
                     pwlo + base + WOFF_G, WSZ_G);
        launch_split(Wu + (long)l * WSZ_U, pwhi + base + WOFF_U,
                     pwlo + base + WOFF_U, WSZ_U);
        launch_split(Wd + (long)l * WSZ_D, pwhi + base + WOFF_D,
                     pwlo + base + WOFF_D, WSZ_D);
    }

    embed_kernel<<<(MTOK * DM + 255) / 256, 256>>>(cls_tokens, cls_token);

    for (int l = 0; l < NL; l++) {
        long wb = (long)l * WSZ_LAYER;
        // ln1 -> split activations
        ln_split_kernel<<<MTOK, 256>>>(px, ln1w + l * DM, ln1b + l * DM,
                                       pahi, palo);
        // QKV projection -> split bf16 qkv
        gemm_bf16<2><<<dim3(3 * DM / 128, MTOK / 128), 256, GB_SMEM>>>(
            pahi, palo, pwhi + wb + WOFF_QKV, pwlo + wb + WOFF_QKV,
            nullptr, nullptr, pqh, pql, 3 * DM, DM);
        // attention -> split bf16 output
        attn_tc<<<dim3(SEQ / 64, NB * NH), 128, AT_SMEM>>>(
            log_slopes, pqh, pql, pahi, palo);
        // out projection + residual
        gemm_bf16<1><<<dim3(DM / 128, MTOK / 128), 256, GB_SMEM>>>(
            pahi, palo, pwhi + wb + WOFF_O, pwlo + wb + WOFF_O,
            px, px, nullptr, nullptr, DM, DM);
        // ln2 -> split activations
        ln_split_kernel<<<MTOK, 256>>>(px, ln2w + l * DM, ln2b + l * DM,
                                       pahi, palo);
        // gate, up
        gemm_bf16<0><<<dim3(DFF / 128, MTOK / 128), 256, GB_SMEM>>>(
            pahi, palo, pwhi + wb + WOFF_G, pwlo + wb + WOFF_G,
            nullptr, pact, nullptr, nullptr, DFF, DM);
        gemm_bf16<0><<<dim3(DFF / 128, MTOK / 128), 256, GB_SMEM>>>(
            pahi, palo, pwhi + wb + WOFF_U, pwlo + wb + WOFF_U,
            nullptr, pup, nullptr, nullptr, DFF, DM);
        // silu(gate)*up -> split activations
        silu_split_kernel<<<(MTOK * DFF / 4 + 255) / 256, 256>>>();
        // down projection + residual
        gemm_bf16<1><<<dim3(DM / 128, MTOK / 128), 256, GB_SMEM>>>(
            pahi, palo, pwhi + wb + WOFF_D, pwlo + wb + WOFF_D,
            px, px, nullptr, nullptr, DM, DFF);
    }

    ln_final_kernel<<<NB, 256>>>(px, SEQ * DM, out, finw, finb);
}